// round 2
// baseline (speedup 1.0000x reference)
#include <cuda_runtime.h>
#include <cstdint>

#define MAX_N 50048
#define MAX_E 800000
#define HID 128
#define NG 64

// ---------------- scratch (device globals; no allocation allowed) ------------
__device__ float g_h[(size_t)MAX_N * HID];
__device__ float g_hh[(size_t)MAX_N * HID];
__device__ float g_esrc[MAX_N * 4];
__device__ float g_edst[MAX_N * 4];
__device__ float g_m[MAX_N * 4];
__device__ float g_denom[MAX_N * 4];
__device__ float g_out[(size_t)MAX_N * HID];
__device__ float g_pooled[NG * HID];
__device__ int   g_counts[NG];

// ---------------- helpers ----------------------------------------------------
__device__ __forceinline__ unsigned long long pk2(float lo, float hi) {
    unsigned long long r;
    asm("mov.b64 %0, {%1,%2};" : "=l"(r) : "f"(lo), "f"(hi));
    return r;
}
__device__ __forceinline__ void fma2(unsigned long long& d, unsigned long long a,
                                     unsigned long long b) {
    asm("fma.rn.f32x2 %0, %1, %2, %0;" : "+l"(d) : "l"(a), "l"(b));
}
__device__ __forceinline__ float2 upk(unsigned long long v) {
    float2 r;
    asm("mov.b64 {%0,%1}, %2;" : "=f"(r.x), "=f"(r.y) : "l"(v));
    return r;
}
__device__ __forceinline__ void red_add_v4(float* addr, float4 v) {
    asm volatile("red.global.add.v4.f32 [%0], {%1,%2,%3,%4};"
                 :: "l"(addr), "f"(v.x), "f"(v.y), "f"(v.z), "f"(v.w) : "memory");
}
__device__ __forceinline__ float lrelu(float x) { return x > 0.f ? x : 0.2f * x; }

__device__ __forceinline__ void atomicMaxF(float* addr, float v) {
    // init pattern is 0xFFFFFFFF (NaN; signed -1; unsigned max) -> behaves as -inf
    if (v > 0.0f) atomicMax((int*)addr, __float_as_int(v));
    else          atomicMin((unsigned int*)addr, __float_as_uint(v));
}

// ---------------- GEMM: C[N,128] = A[N,128] @ W[128,128] (+bias) --------------
__global__ __launch_bounds__(256) void gemm128(const float* __restrict__ A,
                                               const float* __restrict__ W,
                                               const float* __restrict__ bias,
                                               float* __restrict__ C, int N) {
    extern __shared__ float sm[];
    float* At = sm;            // [k][r] transposed A tile, 128x128
    float* Ws = sm + 16384;    // [k][c] W, 128x128
    const int t = threadIdx.x;
    const int row0 = blockIdx.x * 128;

    const float4* Wg = (const float4*)W;
    float4* Wsv = (float4*)Ws;
#pragma unroll
    for (int i = 0; i < 16; i++) Wsv[t + i * 256] = Wg[t + i * 256];

#pragma unroll
    for (int i = 0; i < 16; i++) {
        int idx = t + i * 256;     // 0..4095
        int k4 = idx >> 7;         // 0..31
        int r  = idx & 127;
        float4 v = make_float4(0.f, 0.f, 0.f, 0.f);
        if (row0 + r < N) v = *(const float4*)(A + (size_t)(row0 + r) * 128 + k4 * 4);
        At[(k4 * 4 + 0) * 128 + r] = v.x;
        At[(k4 * 4 + 1) * 128 + r] = v.y;
        At[(k4 * 4 + 2) * 128 + r] = v.z;
        At[(k4 * 4 + 3) * 128 + r] = v.w;
    }
    __syncthreads();

    const int tx = t & 15, ty = t >> 4;
    const int cA = tx * 4, cB = tx * 4 + 64;
    const int rA = ty * 4, rB = ty * 4 + 64;

    unsigned long long acc[4][8];
#pragma unroll
    for (int i = 0; i < 4; i++)
#pragma unroll
        for (int j = 0; j < 8; j++) acc[i][j] = 0ull;

#pragma unroll 4
    for (int k = 0; k < 128; k++) {
        ulonglong2 a01 = *(const ulonglong2*)(At + k * 128 + rA);
        ulonglong2 a23 = *(const ulonglong2*)(At + k * 128 + rB);
        float4 w0 = *(const float4*)(Ws + k * 128 + cA);
        float4 w1 = *(const float4*)(Ws + k * 128 + cB);
        unsigned long long ap[4] = {a01.x, a01.y, a23.x, a23.y};
        unsigned long long wp[8] = {pk2(w0.x, w0.x), pk2(w0.y, w0.y),
                                    pk2(w0.z, w0.z), pk2(w0.w, w0.w),
                                    pk2(w1.x, w1.x), pk2(w1.y, w1.y),
                                    pk2(w1.z, w1.z), pk2(w1.w, w1.w)};
#pragma unroll
        for (int i = 0; i < 4; i++)
#pragma unroll
            for (int j = 0; j < 8; j++) fma2(acc[i][j], ap[i], wp[j]);
    }

    float bA[4] = {0.f, 0.f, 0.f, 0.f}, bB[4] = {0.f, 0.f, 0.f, 0.f};
    if (bias) {
        float4 b0 = *(const float4*)(bias + cA);
        float4 b1 = *(const float4*)(bias + cB);
        bA[0] = b0.x; bA[1] = b0.y; bA[2] = b0.z; bA[3] = b0.w;
        bB[0] = b1.x; bB[1] = b1.y; bB[2] = b1.z; bB[3] = b1.w;
    }

#pragma unroll
    for (int i = 0; i < 4; i++) {
        int r0 = (i < 2) ? (rA + 2 * i) : (rB + 2 * (i - 2));
#pragma unroll
        for (int half = 0; half < 2; half++) {
            int r = r0 + half;
            if (row0 + r >= N) continue;
            float o[8];
#pragma unroll
            for (int j = 0; j < 8; j++) {
                float2 v = upk(acc[i][j]);
                o[j] = half ? v.y : v.x;
            }
            float* Cr = C + (size_t)(row0 + r) * 128;
            *(float4*)(Cr + cA) = make_float4(o[0] + bA[0], o[1] + bA[1],
                                              o[2] + bA[2], o[3] + bA[3]);
            *(float4*)(Cr + cB) = make_float4(o[4] + bB[0], o[5] + bB[1],
                                              o[6] + bB[2], o[7] + bB[3]);
        }
    }
}

// ---------------- per-node attention coefficients -----------------------------
__global__ void attn_coef(const float* __restrict__ hh,
                          const float* __restrict__ a_src,
                          const float* __restrict__ a_dst,
                          float* __restrict__ esrc, float* __restrict__ edst, int N) {
    __shared__ float sa[128], sd[128];
    if (threadIdx.x < 128) { sa[threadIdx.x] = a_src[threadIdx.x]; sd[threadIdx.x] = a_dst[threadIdx.x]; }
    __syncthreads();
    int tid = blockIdx.x * blockDim.x + threadIdx.x;
    int n = tid >> 2, h = tid & 3;
    if (n >= N) return;
    const float4* hp = (const float4*)(hh + (size_t)n * 128 + h * 32);
    const float4* ap = (const float4*)(sa) + h * 8;
    const float4* dp = (const float4*)(sd) + h * 8;
    float s1 = 0.f, s2 = 0.f;
#pragma unroll
    for (int q = 0; q < 8; q++) {
        float4 v = hp[q], a = ap[q], b = dp[q];
        s1 += v.x * a.x + v.y * a.y + v.z * a.z + v.w * a.w;
        s2 += v.x * b.x + v.y * b.y + v.z * b.z + v.w * b.w;
    }
    esrc[n * 4 + h] = s1;
    edst[n * 4 + h] = s2;
}

// ---------------- edge passes (int32 indices!) --------------------------------
__global__ void edge_max(const int* __restrict__ ei,
                         const float* __restrict__ esrc, const float* __restrict__ edst,
                         float* __restrict__ m, int E) {
    int e = blockIdx.x * blockDim.x + threadIdx.x;
    if (e >= E) return;
    int s = ei[e], d = ei[E + e];
    float4 a = *(const float4*)(esrc + s * 4);
    float4 b = *(const float4*)(edst + d * 4);
    atomicMaxF(m + d * 4 + 0, lrelu(a.x + b.x));
    atomicMaxF(m + d * 4 + 1, lrelu(a.y + b.y));
    atomicMaxF(m + d * 4 + 2, lrelu(a.z + b.z));
    atomicMaxF(m + d * 4 + 3, lrelu(a.w + b.w));
}

__global__ void edge_denom(const int* __restrict__ ei,
                           const float* __restrict__ esrc, const float* __restrict__ edst,
                           const float* __restrict__ m, float* __restrict__ denom, int E) {
    int e = blockIdx.x * blockDim.x + threadIdx.x;
    if (e >= E) return;
    int s = ei[e], d = ei[E + e];
    float4 a = *(const float4*)(esrc + s * 4);
    float4 b = *(const float4*)(edst + d * 4);
    float4 mm = *(const float4*)(m + d * 4);
    float4 ex = make_float4(__expf(lrelu(a.x + b.x) - mm.x),
                            __expf(lrelu(a.y + b.y) - mm.y),
                            __expf(lrelu(a.z + b.z) - mm.z),
                            __expf(lrelu(a.w + b.w) - mm.w));
    red_add_v4(denom + d * 4, ex);
}

// warp per edge: gather hh[src] (512B coalesced), scatter alpha*hh into out[dst]
__global__ void edge_agg(const int* __restrict__ ei,
                         const float* __restrict__ esrc, const float* __restrict__ edst,
                         const float* __restrict__ m, const float* __restrict__ denom,
                         const float* __restrict__ hh, float* __restrict__ out, int E) {
    int gid = blockIdx.x * blockDim.x + threadIdx.x;
    int e = gid >> 5, lane = gid & 31;
    if (e >= E) return;
    int s = ei[e], d = ei[E + e];
    int h = lane >> 3;
    float ev = lrelu(esrc[s * 4 + h] + edst[d * 4 + h]);
    float alpha = __expf(ev - m[d * 4 + h]) / denom[d * 4 + h];
    float4 hv = *(const float4*)(hh + (size_t)s * 128 + lane * 4);
    red_add_v4(out + (size_t)d * 128 + lane * 4,
               make_float4(alpha * hv.x, alpha * hv.y, alpha * hv.z, alpha * hv.w));
}

// ---------------- pooling -----------------------------------------------------
__global__ void pool_kernel(const float* __restrict__ out,
                            const int* __restrict__ batch,
                            float* __restrict__ pooled, int* __restrict__ counts, int N) {
    int gid = blockIdx.x * blockDim.x + threadIdx.x;
    int n = gid >> 5, lane = gid & 31;
    if (n >= N) return;
    int g = batch[n];
    float4 v = *(const float4*)(out + (size_t)n * 128 + lane * 4);
    red_add_v4(pooled + g * 128 + lane * 4, v);
    if (lane == 0) atomicAdd(counts + g, 1);
}

// ---------------- classifier --------------------------------------------------
__global__ __launch_bounds__(64) void classifier(const float* __restrict__ pooled,
                                                 const int* __restrict__ counts,
                                                 const float* __restrict__ Wc1,
                                                 const float* __restrict__ bc1,
                                                 const float* __restrict__ Wc2,
                                                 const float* __restrict__ bc2,
                                                 float* __restrict__ outp) {
    __shared__ float sW1[128 * 64];
    __shared__ float sW2[128];
    __shared__ float sb1[64];
    int t = threadIdx.x;  // 64 threads, one graph each
    for (int i = t; i < 8192; i += 64) sW1[i] = Wc1[i];
    for (int i = t; i < 128; i += 64) sW2[i] = Wc2[i];
    sb1[t] = bc1[t];
    __syncthreads();

    float inv = 1.0f / fmaxf((float)counts[t], 1.0f);
    float row[128];
#pragma unroll
    for (int k = 0; k < 128; k++) row[k] = pooled[t * 128 + k] * inv;

    float o0 = bc2[0], o1 = bc2[1];
    for (int j = 0; j < 64; j++) {
        float s = sb1[j];
#pragma unroll
        for (int k = 0; k < 128; k++) s += row[k] * sW1[k * 64 + j];
        s = fmaxf(s, 0.f);
        o0 += s * sW2[j * 2];
        o1 += s * sW2[j * 2 + 1];
    }
    outp[t * 2 + 0] = o0;
    outp[t * 2 + 1] = o1;
}

// ---------------- launch ------------------------------------------------------
extern "C" void kernel_launch(void* const* d_in, const int* in_sizes, int n_in,
                              void* d_out, int out_size) {
    const float* x      = (const float*)d_in[0];
    const int*   ei     = (const int*)d_in[1];
    const int*   batch  = (const int*)d_in[2];
    const float* W_proj = (const float*)d_in[3];
    const float* b_proj = (const float*)d_in[4];
    const float* W_gat  = (const float*)d_in[5];
    const float* a_src  = (const float*)d_in[6];
    const float* a_dst  = (const float*)d_in[7];
    const float* Wc1    = (const float*)d_in[8];
    const float* bc1    = (const float*)d_in[9];
    const float* Wc2    = (const float*)d_in[10];
    const float* bc2    = (const float*)d_in[11];

    int N = in_sizes[0] / 128;
    int E = in_sizes[1] / 2;

    float *p_h, *p_hh, *p_esrc, *p_edst, *p_m, *p_denom, *p_out, *p_pooled;
    int* p_counts;
    cudaGetSymbolAddress((void**)&p_h, g_h);
    cudaGetSymbolAddress((void**)&p_hh, g_hh);
    cudaGetSymbolAddress((void**)&p_esrc, g_esrc);
    cudaGetSymbolAddress((void**)&p_edst, g_edst);
    cudaGetSymbolAddress((void**)&p_m, g_m);
    cudaGetSymbolAddress((void**)&p_denom, g_denom);
    cudaGetSymbolAddress((void**)&p_out, g_out);
    cudaGetSymbolAddress((void**)&p_pooled, g_pooled);
    cudaGetSymbolAddress((void**)&p_counts, g_counts);

    cudaFuncSetAttribute(gemm128, cudaFuncAttributeMaxDynamicSharedMemorySize, 131072);

    cudaMemsetAsync(p_out, 0, (size_t)N * 128 * sizeof(float));
    cudaMemsetAsync(p_denom, 0, (size_t)N * 4 * sizeof(float));
    cudaMemsetAsync(p_m, 0xFF, (size_t)N * 4 * sizeof(float));
    cudaMemsetAsync(p_pooled, 0, NG * 128 * sizeof(float));
    cudaMemsetAsync(p_counts, 0, NG * sizeof(int));

    int gb = (N + 127) / 128;
    gemm128<<<gb, 256, 131072>>>(x, W_proj, b_proj, p_h, N);
    gemm128<<<gb, 256, 131072>>>(p_h, W_gat, nullptr, p_hh, N);
    attn_coef<<<(N * 4 + 255) / 256, 256>>>(p_hh, a_src, a_dst, p_esrc, p_edst, N);
    edge_max<<<(E + 255) / 256, 256>>>(ei, p_esrc, p_edst, p_m, E);
    edge_denom<<<(E + 255) / 256, 256>>>(ei, p_esrc, p_edst, p_m, p_denom, E);
    edge_agg<<<((size_t)E * 32 + 255) / 256, 256>>>(ei, p_esrc, p_edst, p_m, p_denom,
                                                    p_hh, p_out, E);
    pool_kernel<<<((size_t)N * 32 + 255) / 256, 256>>>(p_out, batch, p_pooled, p_counts, N);
    classifier<<<1, 64>>>(p_pooled, p_counts, Wc1, bc1, Wc2, bc2, (float*)d_out);
}

// round 3
// speedup vs baseline: 1.2184x; 1.2184x over previous
#include <cuda_runtime.h>
#include <cstdint>

#define MAX_N 50048
#define MAX_E 800000
#define HID 128
#define NG 64

// ---------------- scratch (device globals; no allocation allowed) ------------
__device__ float g_h[(size_t)MAX_N * HID];
__device__ float g_hh[(size_t)MAX_N * HID];
__device__ float g_esrc[MAX_N * 4];
__device__ float g_edst[MAX_N * 4];
__device__ int   g_deg[MAX_N];
__device__ int   g_off[MAX_N + 1];
__device__ int   g_pos[MAX_E];
__device__ int   g_srcsort[MAX_E];
__device__ float g_pooled[NG * HID];
__device__ int   g_counts[NG];

// ---------------- helpers ----------------------------------------------------
__device__ __forceinline__ unsigned long long pk2(float lo, float hi) {
    unsigned long long r;
    asm("mov.b64 %0, {%1,%2};" : "=l"(r) : "f"(lo), "f"(hi));
    return r;
}
__device__ __forceinline__ void fma2(unsigned long long& d, unsigned long long a,
                                     unsigned long long b) {
    asm("fma.rn.f32x2 %0, %1, %2, %0;" : "+l"(d) : "l"(a), "l"(b));
}
__device__ __forceinline__ float2 upk(unsigned long long v) {
    float2 r;
    asm("mov.b64 {%0,%1}, %2;" : "=f"(r.x), "=f"(r.y) : "l"(v));
    return r;
}
__device__ __forceinline__ void red_add_v4(float* addr, float4 v) {
    asm volatile("red.global.add.v4.f32 [%0], {%1,%2,%3,%4};"
                 :: "l"(addr), "f"(v.x), "f"(v.y), "f"(v.z), "f"(v.w) : "memory");
}
__device__ __forceinline__ float lrelu(float x) { return x > 0.f ? x : 0.2f * x; }

// ---------------- GEMM: C[N,128] = A[N,128] @ W[128,128] (+bias) --------------
__global__ __launch_bounds__(256) void gemm128(const float* __restrict__ A,
                                               const float* __restrict__ W,
                                               const float* __restrict__ bias,
                                               float* __restrict__ C, int N) {
    extern __shared__ float sm[];
    float* At = sm;            // [k][r] transposed A tile, 128x128
    float* Ws = sm + 16384;    // [k][c] W, 128x128
    const int t = threadIdx.x;
    const int row0 = blockIdx.x * 128;

    const float4* Wg = (const float4*)W;
    float4* Wsv = (float4*)Ws;
#pragma unroll
    for (int i = 0; i < 16; i++) Wsv[t + i * 256] = Wg[t + i * 256];

#pragma unroll
    for (int i = 0; i < 16; i++) {
        int idx = t + i * 256;     // 0..4095
        int k4 = idx >> 7;         // 0..31
        int r  = idx & 127;
        float4 v = make_float4(0.f, 0.f, 0.f, 0.f);
        if (row0 + r < N) v = *(const float4*)(A + (size_t)(row0 + r) * 128 + k4 * 4);
        At[(k4 * 4 + 0) * 128 + r] = v.x;
        At[(k4 * 4 + 1) * 128 + r] = v.y;
        At[(k4 * 4 + 2) * 128 + r] = v.z;
        At[(k4 * 4 + 3) * 128 + r] = v.w;
    }
    __syncthreads();

    const int tx = t & 15, ty = t >> 4;
    const int cA = tx * 4, cB = tx * 4 + 64;
    const int rA = ty * 4, rB = ty * 4 + 64;

    unsigned long long acc[4][8];
#pragma unroll
    for (int i = 0; i < 4; i++)
#pragma unroll
        for (int j = 0; j < 8; j++) acc[i][j] = 0ull;

#pragma unroll 4
    for (int k = 0; k < 128; k++) {
        ulonglong2 a01 = *(const ulonglong2*)(At + k * 128 + rA);
        ulonglong2 a23 = *(const ulonglong2*)(At + k * 128 + rB);
        float4 w0 = *(const float4*)(Ws + k * 128 + cA);
        float4 w1 = *(const float4*)(Ws + k * 128 + cB);
        unsigned long long ap[4] = {a01.x, a01.y, a23.x, a23.y};
        unsigned long long wp[8] = {pk2(w0.x, w0.x), pk2(w0.y, w0.y),
                                    pk2(w0.z, w0.z), pk2(w0.w, w0.w),
                                    pk2(w1.x, w1.x), pk2(w1.y, w1.y),
                                    pk2(w1.z, w1.z), pk2(w1.w, w1.w)};
#pragma unroll
        for (int i = 0; i < 4; i++)
#pragma unroll
            for (int j = 0; j < 8; j++) fma2(acc[i][j], ap[i], wp[j]);
    }

    float bA[4] = {0.f, 0.f, 0.f, 0.f}, bB[4] = {0.f, 0.f, 0.f, 0.f};
    if (bias) {
        float4 b0 = *(const float4*)(bias + cA);
        float4 b1 = *(const float4*)(bias + cB);
        bA[0] = b0.x; bA[1] = b0.y; bA[2] = b0.z; bA[3] = b0.w;
        bB[0] = b1.x; bB[1] = b1.y; bB[2] = b1.z; bB[3] = b1.w;
    }

#pragma unroll
    for (int i = 0; i < 4; i++) {
        int r0 = (i < 2) ? (rA + 2 * i) : (rB + 2 * (i - 2));
#pragma unroll
        for (int half = 0; half < 2; half++) {
            int r = r0 + half;
            if (row0 + r >= N) continue;
            float o[8];
#pragma unroll
            for (int j = 0; j < 8; j++) {
                float2 v = upk(acc[i][j]);
                o[j] = half ? v.y : v.x;
            }
            float* Cr = C + (size_t)(row0 + r) * 128;
            *(float4*)(Cr + cA) = make_float4(o[0] + bA[0], o[1] + bA[1],
                                              o[2] + bA[2], o[3] + bA[3]);
            *(float4*)(Cr + cB) = make_float4(o[4] + bB[0], o[5] + bB[1],
                                              o[6] + bB[2], o[7] + bB[3]);
        }
    }
}

// ---------------- per-node attention coefficients -----------------------------
__global__ void attn_coef(const float* __restrict__ hh,
                          const float* __restrict__ a_src,
                          const float* __restrict__ a_dst,
                          float* __restrict__ esrc, float* __restrict__ edst, int N) {
    __shared__ float sa[128], sd[128];
    if (threadIdx.x < 128) { sa[threadIdx.x] = a_src[threadIdx.x]; sd[threadIdx.x] = a_dst[threadIdx.x]; }
    __syncthreads();
    int tid = blockIdx.x * blockDim.x + threadIdx.x;
    int n = tid >> 2, h = tid & 3;
    if (n >= N) return;
    const float4* hp = (const float4*)(hh + (size_t)n * 128 + h * 32);
    const float4* ap = (const float4*)(sa) + h * 8;
    const float4* dp = (const float4*)(sd) + h * 8;
    float s1 = 0.f, s2 = 0.f;
#pragma unroll
    for (int q = 0; q < 8; q++) {
        float4 v = hp[q], a = ap[q], b = dp[q];
        s1 += v.x * a.x + v.y * a.y + v.z * a.z + v.w * a.w;
        s2 += v.x * b.x + v.y * b.y + v.z * b.z + v.w * b.w;
    }
    esrc[n * 4 + h] = s1;
    edst[n * 4 + h] = s2;
}

// ---------------- CSR build ---------------------------------------------------
__global__ void hist_kernel(const int* __restrict__ ei, int* __restrict__ deg,
                            int* __restrict__ pos, int E) {
    int e = blockIdx.x * blockDim.x + threadIdx.x;
    if (e >= E) return;
    int d = ei[E + e];
    pos[e] = atomicAdd(deg + d, 1);
}

__global__ __launch_bounds__(1024) void scan_kernel(const int* __restrict__ deg,
                                                    int* __restrict__ off, int N) {
    __shared__ int ssum[1024];
    int t = threadIdx.x;
    int chunk = (N + 1023) / 1024;
    int b = t * chunk;
    int e = min(b + chunk, N);
    int s = 0;
    for (int i = b; i < e; i++) s += deg[i];
    ssum[t] = s;
    __syncthreads();
    for (int d = 1; d < 1024; d <<= 1) {
        int v = (t >= d) ? ssum[t - d] : 0;
        __syncthreads();
        ssum[t] += v;
        __syncthreads();
    }
    int base = (t == 0) ? 0 : ssum[t - 1];
    for (int i = b; i < e; i++) { off[i] = base; base += deg[i]; }
    if (t == 1023) off[N] = base;
}

__global__ void scatter_kernel(const int* __restrict__ ei, const int* __restrict__ off,
                               const int* __restrict__ pos, int* __restrict__ srcs, int E) {
    int e = blockIdx.x * blockDim.x + threadIdx.x;
    if (e >= E) return;
    int s = ei[e], d = ei[E + e];
    srcs[off[d] + pos[e]] = s;
}

// ---------------- fused softmax + aggregate + pool (warp per dst node) --------
__global__ __launch_bounds__(256) void agg_fused(const int* __restrict__ off,
                                                 const int* __restrict__ srcs,
                                                 const float* __restrict__ esrc,
                                                 const float* __restrict__ edst,
                                                 const float* __restrict__ hh,
                                                 const int* __restrict__ batch,
                                                 float* __restrict__ pooled,
                                                 int* __restrict__ counts, int N) {
    int w = (blockIdx.x * blockDim.x + threadIdx.x) >> 5;
    int lane = threadIdx.x & 31;
    if (w >= N) return;
    int g = batch[w];
    if (lane == 0) atomicAdd(counts + g, 1);
    int beg = off[w], end = off[w + 1];
    if (beg == end) return;

    float4 b = *(const float4*)(edst + w * 4);

    // pass A: softmax denominator per head (no max shift; |e| is O(1))
    float4 dsum = make_float4(0.f, 0.f, 0.f, 0.f);
    for (int i = beg + lane; i < end; i += 32) {
        int s = srcs[i];
        float4 a = *(const float4*)(esrc + s * 4);
        dsum.x += __expf(lrelu(a.x + b.x));
        dsum.y += __expf(lrelu(a.y + b.y));
        dsum.z += __expf(lrelu(a.z + b.z));
        dsum.w += __expf(lrelu(a.w + b.w));
    }
#pragma unroll
    for (int d = 16; d; d >>= 1) {
        dsum.x += __shfl_xor_sync(0xFFFFFFFFu, dsum.x, d);
        dsum.y += __shfl_xor_sync(0xFFFFFFFFu, dsum.y, d);
        dsum.z += __shfl_xor_sync(0xFFFFFFFFu, dsum.z, d);
        dsum.w += __shfl_xor_sync(0xFFFFFFFFu, dsum.w, d);
    }

    int h = lane >> 3;
    float bh   = (h == 0) ? b.x : (h == 1) ? b.y : (h == 2) ? b.z : b.w;
    float dh   = (h == 0) ? dsum.x : (h == 1) ? dsum.y : (h == 2) ? dsum.z : dsum.w;
    float inv  = 1.0f / dh;

    // pass B: gather hh[src] rows, weight by alpha, accumulate
    float4 acc = make_float4(0.f, 0.f, 0.f, 0.f);
    for (int i = beg; i < end; i++) {
        int s = srcs[i];
        float alpha = __expf(lrelu(esrc[s * 4 + h] + bh)) * inv;
        float4 hv = *(const float4*)(hh + (size_t)s * 128 + lane * 4);
        acc.x += alpha * hv.x;
        acc.y += alpha * hv.y;
        acc.z += alpha * hv.z;
        acc.w += alpha * hv.w;
    }
    red_add_v4(pooled + g * 128 + lane * 4, acc);
}

// ---------------- classifier --------------------------------------------------
__global__ __launch_bounds__(64) void classifier(const float* __restrict__ pooled,
                                                 const int* __restrict__ counts,
                                                 const float* __restrict__ Wc1,
                                                 const float* __restrict__ bc1,
                                                 const float* __restrict__ Wc2,
                                                 const float* __restrict__ bc2,
                                                 float* __restrict__ outp) {
    __shared__ float sW1[128 * 64];
    __shared__ float sW2[128];
    __shared__ float sb1[64];
    int t = threadIdx.x;  // 64 threads, one graph each
    for (int i = t; i < 8192; i += 64) sW1[i] = Wc1[i];
    for (int i = t; i < 128; i += 64) sW2[i] = Wc2[i];
    sb1[t] = bc1[t];
    __syncthreads();

    float inv = 1.0f / fmaxf((float)counts[t], 1.0f);
    float row[128];
#pragma unroll
    for (int k = 0; k < 128; k++) row[k] = pooled[t * 128 + k] * inv;

    float o0 = bc2[0], o1 = bc2[1];
    for (int j = 0; j < 64; j++) {
        float s = sb1[j];
#pragma unroll
        for (int k = 0; k < 128; k++) s += row[k] * sW1[k * 64 + j];
        s = fmaxf(s, 0.f);
        o0 += s * sW2[j * 2];
        o1 += s * sW2[j * 2 + 1];
    }
    outp[t * 2 + 0] = o0;
    outp[t * 2 + 1] = o1;
}

// ---------------- launch ------------------------------------------------------
extern "C" void kernel_launch(void* const* d_in, const int* in_sizes, int n_in,
                              void* d_out, int out_size) {
    const float* x      = (const float*)d_in[0];
    const int*   ei     = (const int*)d_in[1];
    const int*   batch  = (const int*)d_in[2];
    const float* W_proj = (const float*)d_in[3];
    const float* b_proj = (const float*)d_in[4];
    const float* W_gat  = (const float*)d_in[5];
    const float* a_src  = (const float*)d_in[6];
    const float* a_dst  = (const float*)d_in[7];
    const float* Wc1    = (const float*)d_in[8];
    const float* bc1    = (const float*)d_in[9];
    const float* Wc2    = (const float*)d_in[10];
    const float* bc2    = (const float*)d_in[11];

    int N = in_sizes[0] / 128;
    int E = in_sizes[1] / 2;

    float *p_h, *p_hh, *p_esrc, *p_edst, *p_pooled;
    int *p_deg, *p_off, *p_pos, *p_srcs, *p_counts;
    cudaGetSymbolAddress((void**)&p_h, g_h);
    cudaGetSymbolAddress((void**)&p_hh, g_hh);
    cudaGetSymbolAddress((void**)&p_esrc, g_esrc);
    cudaGetSymbolAddress((void**)&p_edst, g_edst);
    cudaGetSymbolAddress((void**)&p_deg, g_deg);
    cudaGetSymbolAddress((void**)&p_off, g_off);
    cudaGetSymbolAddress((void**)&p_pos, g_pos);
    cudaGetSymbolAddress((void**)&p_srcs, g_srcsort);
    cudaGetSymbolAddress((void**)&p_pooled, g_pooled);
    cudaGetSymbolAddress((void**)&p_counts, g_counts);

    cudaFuncSetAttribute(gemm128, cudaFuncAttributeMaxDynamicSharedMemorySize, 131072);

    cudaMemsetAsync(p_deg, 0, (size_t)N * sizeof(int));
    cudaMemsetAsync(p_pooled, 0, NG * HID * sizeof(float));
    cudaMemsetAsync(p_counts, 0, NG * sizeof(int));

    int gb = (N + 127) / 128;
    gemm128<<<gb, 256, 131072>>>(x, W_proj, b_proj, p_h, N);
    gemm128<<<gb, 256, 131072>>>(p_h, W_gat, nullptr, p_hh, N);
    attn_coef<<<(N * 4 + 255) / 256, 256>>>(p_hh, a_src, a_dst, p_esrc, p_edst, N);
    hist_kernel<<<(E + 255) / 256, 256>>>(ei, p_deg, p_pos, E);
    scan_kernel<<<1, 1024>>>(p_deg, p_off, N);
    scatter_kernel<<<(E + 255) / 256, 256>>>(ei, p_off, p_pos, p_srcs, E);
    agg_fused<<<((size_t)N * 32 + 255) / 256, 256>>>(p_off, p_srcs, p_esrc, p_edst,
                                                     p_hh, batch, p_pooled, p_counts, N);
    classifier<<<1, 64>>>(p_pooled, p_counts, Wc1, bc1, Wc2, bc2, (float*)d_out);
}

// round 4
// speedup vs baseline: 1.6486x; 1.3530x over previous
#include <cuda_runtime.h>
#include <cstdint>

#define MAX_N 50048
#define MAX_E 800000
#define HID 128
#define NG 64

// ---------------- scratch (device globals; no allocation allowed) ------------
__device__ float g_hh[(size_t)MAX_N * HID];
__device__ float g_Wcomb[HID * HID];
__device__ float g_bcomb[HID];
__device__ float g_esrc[MAX_N * 4];
__device__ float g_edst[MAX_N * 4];
__device__ int   g_deg[MAX_N];
__device__ int   g_off[MAX_N + 1];
__device__ int   g_cursor[MAX_N];
__device__ int   g_srcsort[MAX_E];
__device__ int   g_bsum[64];
__device__ int   g_gbase[64];
__device__ float g_pooled[NG * HID];
__device__ int   g_counts[NG];

// ---------------- helpers ----------------------------------------------------
__device__ __forceinline__ unsigned long long pk2(float lo, float hi) {
    unsigned long long r;
    asm("mov.b64 %0, {%1,%2};" : "=l"(r) : "f"(lo), "f"(hi));
    return r;
}
__device__ __forceinline__ void fma2(unsigned long long& d, unsigned long long a,
                                     unsigned long long b) {
    asm("fma.rn.f32x2 %0, %1, %2, %0;" : "+l"(d) : "l"(a), "l"(b));
}
__device__ __forceinline__ float2 upk(unsigned long long v) {
    float2 r;
    asm("mov.b64 {%0,%1}, %2;" : "=f"(r.x), "=f"(r.y) : "l"(v));
    return r;
}
__device__ __forceinline__ void red_add_v4(float* addr, float4 v) {
    asm volatile("red.global.add.v4.f32 [%0], {%1,%2,%3,%4};"
                 :: "l"(addr), "f"(v.x), "f"(v.y), "f"(v.z), "f"(v.w) : "memory");
}
__device__ __forceinline__ float lrelu(float x) { return x > 0.f ? x : 0.2f * x; }

// ---------------- GEMM: C[N,128] = A[N,128] @ W[128,128] (+bias) --------------
__global__ __launch_bounds__(256) void gemm128(const float* __restrict__ A,
                                               const float* __restrict__ W,
                                               const float* __restrict__ bias,
                                               float* __restrict__ C, int N) {
    extern __shared__ float sm[];
    float* At = sm;            // [k][r] transposed A tile, 128x128
    float* Ws = sm + 16384;    // [k][c] W, 128x128
    const int t = threadIdx.x;
    const int row0 = blockIdx.x * 128;

    const float4* Wg = (const float4*)W;
    float4* Wsv = (float4*)Ws;
#pragma unroll
    for (int i = 0; i < 16; i++) Wsv[t + i * 256] = Wg[t + i * 256];

#pragma unroll
    for (int i = 0; i < 16; i++) {
        int idx = t + i * 256;     // 0..4095
        int k4 = idx >> 7;         // 0..31
        int r  = idx & 127;
        float4 v = make_float4(0.f, 0.f, 0.f, 0.f);
        if (row0 + r < N) v = *(const float4*)(A + (size_t)(row0 + r) * 128 + k4 * 4);
        At[(k4 * 4 + 0) * 128 + r] = v.x;
        At[(k4 * 4 + 1) * 128 + r] = v.y;
        At[(k4 * 4 + 2) * 128 + r] = v.z;
        At[(k4 * 4 + 3) * 128 + r] = v.w;
    }
    __syncthreads();

    const int tx = t & 15, ty = t >> 4;
    const int cA = tx * 4, cB = tx * 4 + 64;
    const int rA = ty * 4, rB = ty * 4 + 64;

    unsigned long long acc[4][8];
#pragma unroll
    for (int i = 0; i < 4; i++)
#pragma unroll
        for (int j = 0; j < 8; j++) acc[i][j] = 0ull;

#pragma unroll 4
    for (int k = 0; k < 128; k++) {
        ulonglong2 a01 = *(const ulonglong2*)(At + k * 128 + rA);
        ulonglong2 a23 = *(const ulonglong2*)(At + k * 128 + rB);
        float4 w0 = *(const float4*)(Ws + k * 128 + cA);
        float4 w1 = *(const float4*)(Ws + k * 128 + cB);
        unsigned long long ap[4] = {a01.x, a01.y, a23.x, a23.y};
        unsigned long long wp[8] = {pk2(w0.x, w0.x), pk2(w0.y, w0.y),
                                    pk2(w0.z, w0.z), pk2(w0.w, w0.w),
                                    pk2(w1.x, w1.x), pk2(w1.y, w1.y),
                                    pk2(w1.z, w1.z), pk2(w1.w, w1.w)};
#pragma unroll
        for (int i = 0; i < 4; i++)
#pragma unroll
            for (int j = 0; j < 8; j++) fma2(acc[i][j], ap[i], wp[j]);
    }

    float bA[4] = {0.f, 0.f, 0.f, 0.f}, bB[4] = {0.f, 0.f, 0.f, 0.f};
    if (bias) {
        float4 b0 = *(const float4*)(bias + cA);
        float4 b1 = *(const float4*)(bias + cB);
        bA[0] = b0.x; bA[1] = b0.y; bA[2] = b0.z; bA[3] = b0.w;
        bB[0] = b1.x; bB[1] = b1.y; bB[2] = b1.z; bB[3] = b1.w;
    }

#pragma unroll
    for (int i = 0; i < 4; i++) {
        int r0 = (i < 2) ? (rA + 2 * i) : (rB + 2 * (i - 2));
#pragma unroll
        for (int half = 0; half < 2; half++) {
            int r = r0 + half;
            if (row0 + r >= N) continue;
            float o[8];
#pragma unroll
            for (int j = 0; j < 8; j++) {
                float2 v = upk(acc[i][j]);
                o[j] = half ? v.y : v.x;
            }
            float* Cr = C + (size_t)(row0 + r) * 128;
            *(float4*)(Cr + cA) = make_float4(o[0] + bA[0], o[1] + bA[1],
                                              o[2] + bA[2], o[3] + bA[3]);
            *(float4*)(Cr + cB) = make_float4(o[4] + bB[0], o[5] + bB[1],
                                              o[6] + bB[2], o[7] + bB[3]);
        }
    }
}

// ---------------- combined bias: b_comb = b_proj @ W_gat ----------------------
__global__ __launch_bounds__(128) void bias_comb(const float* __restrict__ b_proj,
                                                 const float* __restrict__ W_gat,
                                                 float* __restrict__ b_comb) {
    int c = threadIdx.x;
    float s = 0.f;
#pragma unroll 8
    for (int k = 0; k < 128; k++) s += b_proj[k] * W_gat[k * 128 + c];
    b_comb[c] = s;
}

// ---------------- per-node attention coefficients -----------------------------
__global__ void attn_coef(const float* __restrict__ hh,
                          const float* __restrict__ a_src,
                          const float* __restrict__ a_dst,
                          float* __restrict__ esrc, float* __restrict__ edst, int N) {
    __shared__ float sa[128], sd[128];
    if (threadIdx.x < 128) { sa[threadIdx.x] = a_src[threadIdx.x]; sd[threadIdx.x] = a_dst[threadIdx.x]; }
    __syncthreads();
    int tid = blockIdx.x * blockDim.x + threadIdx.x;
    int n = tid >> 2, h = tid & 3;
    if (n >= N) return;
    const float4* hp = (const float4*)(hh + (size_t)n * 128 + h * 32);
    const float4* ap = (const float4*)(sa) + h * 8;
    const float4* dp = (const float4*)(sd) + h * 8;
    float s1 = 0.f, s2 = 0.f;
#pragma unroll
    for (int q = 0; q < 8; q++) {
        float4 v = hp[q], a = ap[q], b = dp[q];
        s1 += v.x * a.x + v.y * a.y + v.z * a.z + v.w * a.w;
        s2 += v.x * b.x + v.y * b.y + v.z * b.z + v.w * b.w;
    }
    esrc[n * 4 + h] = s1;
    edst[n * 4 + h] = s2;
}

// ---------------- CSR build ---------------------------------------------------
// histogram: fire-and-forget REDs, 4-edge ILP
__global__ void hist_kernel(const int* __restrict__ ei, int* __restrict__ deg, int E) {
    int base = (blockIdx.x * blockDim.x + threadIdx.x) * 4;
    if (base >= E) return;
#pragma unroll
    for (int j = 0; j < 4; j++) {
        int e = base + j;
        if (e < E) atomicAdd(deg + ei[E + e], 1);  // result unused -> RED
    }
}

// scan stage 1: per-1024-chunk exclusive scan + chunk total
__global__ __launch_bounds__(256) void scan1(const int* __restrict__ deg,
                                             int* __restrict__ off,
                                             int* __restrict__ bsum, int N) {
    __shared__ int sc[256];
    int t = threadIdx.x;
    int base = blockIdx.x * 1024 + t * 4;
    int v[4];
#pragma unroll
    for (int j = 0; j < 4; j++) v[j] = (base + j < N) ? deg[base + j] : 0;
    int s = v[0] + v[1] + v[2] + v[3];
    sc[t] = s;
    __syncthreads();
    for (int d = 1; d < 256; d <<= 1) {
        int val = (t >= d) ? sc[t - d] : 0;
        __syncthreads();
        sc[t] += val;
        __syncthreads();
    }
    if (t == 255) bsum[blockIdx.x] = sc[255];
    int run = (t == 0) ? 0 : sc[t - 1];
#pragma unroll
    for (int j = 0; j < 4; j++) {
        if (base + j < N) off[base + j] = run;
        run += v[j];
    }
}

// scan stage 2: scan chunk totals (<=64 chunks)
__global__ __launch_bounds__(64) void scan2(const int* __restrict__ bsum,
                                            int* __restrict__ gbase, int nb) {
    __shared__ int sc[64];
    int t = threadIdx.x;
    sc[t] = (t < nb) ? bsum[t] : 0;
    __syncthreads();
    for (int d = 1; d < 64; d <<= 1) {
        int val = (t >= d) ? sc[t - d] : 0;
        __syncthreads();
        sc[t] += val;
        __syncthreads();
    }
    gbase[t] = (t == 0) ? 0 : sc[t - 1];
}

// scan stage 3: add chunk bases; write off[N]
__global__ __launch_bounds__(256) void scan3(int* __restrict__ off,
                                             const int* __restrict__ gbase,
                                             int N, int E) {
    int add = gbase[blockIdx.x];
    int base = blockIdx.x * 1024 + threadIdx.x * 4;
#pragma unroll
    for (int j = 0; j < 4; j++)
        if (base + j < N) off[base + j] += add;
    if (blockIdx.x == 0 && threadIdx.x == 0) off[N] = E;
}

// scatter with cursor atomics, 4-edge ILP
__global__ void scatter_kernel(const int* __restrict__ ei, int* __restrict__ cursor,
                               int* __restrict__ srcs, int E) {
    int base = (blockIdx.x * blockDim.x + threadIdx.x) * 4;
    if (base >= E) return;
    int s[4], p[4];
#pragma unroll
    for (int j = 0; j < 4; j++) {
        int e = base + j;
        if (e < E) {
            s[j] = ei[e];
            p[j] = atomicAdd(cursor + ei[E + e], 1);
        }
    }
#pragma unroll
    for (int j = 0; j < 4; j++)
        if (base + j < E) srcs[p[j]] = s[j];
}

// ---------------- fused softmax + aggregate + pool (warp per dst node) --------
#define CAP 128
__global__ __launch_bounds__(256) void agg_fused(const int* __restrict__ off,
                                                 const int* __restrict__ srcs,
                                                 const float* __restrict__ esrc,
                                                 const float* __restrict__ edst,
                                                 const float* __restrict__ hh,
                                                 const int* __restrict__ batch,
                                                 float* __restrict__ pooled,
                                                 int* __restrict__ counts, int N) {
    __shared__ int    sh_src[8][CAP];
    __shared__ float4 sh_ex[8][CAP];
    int wi = threadIdx.x >> 5;
    int w = (blockIdx.x * blockDim.x + threadIdx.x) >> 5;
    int lane = threadIdx.x & 31;
    if (w >= N) return;
    int g = batch[w];
    if (lane == 0) atomicAdd(counts + g, 1);
    int beg = off[w], end = off[w + 1];
    int deg = end - beg;
    if (deg == 0) return;

    float4 b = *(const float4*)(edst + w * 4);

    // pass A: per-edge exp4 (cached in smem) + denominator reduction
    float4 dsum = make_float4(0.f, 0.f, 0.f, 0.f);
    for (int i = lane; i < deg; i += 32) {
        int s = srcs[beg + i];
        float4 a = *(const float4*)(esrc + s * 4);
        float4 ex = make_float4(__expf(lrelu(a.x + b.x)), __expf(lrelu(a.y + b.y)),
                                __expf(lrelu(a.z + b.z)), __expf(lrelu(a.w + b.w)));
        if (i < CAP) { sh_src[wi][i] = s; sh_ex[wi][i] = ex; }
        dsum.x += ex.x; dsum.y += ex.y; dsum.z += ex.z; dsum.w += ex.w;
    }
#pragma unroll
    for (int d = 16; d; d >>= 1) {
        dsum.x += __shfl_xor_sync(0xFFFFFFFFu, dsum.x, d);
        dsum.y += __shfl_xor_sync(0xFFFFFFFFu, dsum.y, d);
        dsum.z += __shfl_xor_sync(0xFFFFFFFFu, dsum.z, d);
        dsum.w += __shfl_xor_sync(0xFFFFFFFFu, dsum.w, d);
    }
    __syncwarp();

    int h = lane >> 3;
    float bh  = (h == 0) ? b.x : (h == 1) ? b.y : (h == 2) ? b.z : b.w;
    float dh  = (h == 0) ? dsum.x : (h == 1) ? dsum.y : (h == 2) ? dsum.z : dsum.w;
    float inv = 1.0f / dh;

    // pass B: gather hh[src] rows weighted by alpha (all operands from smem)
    float4 acc = make_float4(0.f, 0.f, 0.f, 0.f);
    int nfast = (deg < CAP) ? deg : CAP;
#pragma unroll 4
    for (int i = 0; i < nfast; i++) {
        int s = sh_src[wi][i];
        float4 ex = sh_ex[wi][i];
        float alpha = ((h == 0) ? ex.x : (h == 1) ? ex.y : (h == 2) ? ex.z : ex.w) * inv;
        float4 hv = *(const float4*)(hh + (size_t)s * 128 + lane * 4);
        acc.x += alpha * hv.x;
        acc.y += alpha * hv.y;
        acc.z += alpha * hv.z;
        acc.w += alpha * hv.w;
    }
    for (int i = CAP; i < deg; i++) {  // rare overflow path
        int s = srcs[beg + i];
        float alpha = __expf(lrelu(esrc[s * 4 + h] + bh)) * inv;
        float4 hv = *(const float4*)(hh + (size_t)s * 128 + lane * 4);
        acc.x += alpha * hv.x;
        acc.y += alpha * hv.y;
        acc.z += alpha * hv.z;
        acc.w += alpha * hv.w;
    }
    red_add_v4(pooled + g * 128 + lane * 4, acc);
}

// ---------------- classifier --------------------------------------------------
__global__ __launch_bounds__(64) void classifier(const float* __restrict__ pooled,
                                                 const int* __restrict__ counts,
                                                 const float* __restrict__ Wc1,
                                                 const float* __restrict__ bc1,
                                                 const float* __restrict__ Wc2,
                                                 const float* __restrict__ bc2,
                                                 float* __restrict__ outp) {
    __shared__ float sW1[128 * 64];
    __shared__ float sW2[128];
    __shared__ float sb1[64];
    int t = threadIdx.x;  // 64 threads, one graph each
    for (int i = t; i < 8192; i += 64) sW1[i] = Wc1[i];
    for (int i = t; i < 128; i += 64) sW2[i] = Wc2[i];
    sb1[t] = bc1[t];
    __syncthreads();

    float inv = 1.0f / fmaxf((float)counts[t], 1.0f);
    float row[128];
#pragma unroll
    for (int k = 0; k < 128; k++) row[k] = pooled[t * 128 + k] * inv;

    float o0 = bc2[0], o1 = bc2[1];
    for (int j = 0; j < 64; j++) {
        float s = sb1[j];
#pragma unroll
        for (int k = 0; k < 128; k++) s += row[k] * sW1[k * 64 + j];
        s = fmaxf(s, 0.f);
        o0 += s * sW2[j * 2];
        o1 += s * sW2[j * 2 + 1];
    }
    outp[t * 2 + 0] = o0;
    outp[t * 2 + 1] = o1;
}

// ---------------- launch ------------------------------------------------------
extern "C" void kernel_launch(void* const* d_in, const int* in_sizes, int n_in,
                              void* d_out, int out_size) {
    const float* x      = (const float*)d_in[0];
    const int*   ei     = (const int*)d_in[1];
    const int*   batch  = (const int*)d_in[2];
    const float* W_proj = (const float*)d_in[3];
    const float* b_proj = (const float*)d_in[4];
    const float* W_gat  = (const float*)d_in[5];
    const float* a_src  = (const float*)d_in[6];
    const float* a_dst  = (const float*)d_in[7];
    const float* Wc1    = (const float*)d_in[8];
    const float* bc1    = (const float*)d_in[9];
    const float* Wc2    = (const float*)d_in[10];
    const float* bc2    = (const float*)d_in[11];

    int N = in_sizes[0] / 128;
    int E = in_sizes[1] / 2;

    float *p_hh, *p_Wcomb, *p_bcomb, *p_esrc, *p_edst, *p_pooled;
    int *p_deg, *p_off, *p_cursor, *p_srcs, *p_bsum, *p_gbase, *p_counts;
    cudaGetSymbolAddress((void**)&p_hh, g_hh);
    cudaGetSymbolAddress((void**)&p_Wcomb, g_Wcomb);
    cudaGetSymbolAddress((void**)&p_bcomb, g_bcomb);
    cudaGetSymbolAddress((void**)&p_esrc, g_esrc);
    cudaGetSymbolAddress((void**)&p_edst, g_edst);
    cudaGetSymbolAddress((void**)&p_deg, g_deg);
    cudaGetSymbolAddress((void**)&p_off, g_off);
    cudaGetSymbolAddress((void**)&p_cursor, g_cursor);
    cudaGetSymbolAddress((void**)&p_srcs, g_srcsort);
    cudaGetSymbolAddress((void**)&p_bsum, g_bsum);
    cudaGetSymbolAddress((void**)&p_gbase, g_gbase);
    cudaGetSymbolAddress((void**)&p_pooled, g_pooled);
    cudaGetSymbolAddress((void**)&p_counts, g_counts);

    cudaFuncSetAttribute(gemm128, cudaFuncAttributeMaxDynamicSharedMemorySize, 131072);

    cudaMemsetAsync(p_deg, 0, (size_t)N * sizeof(int));
    cudaMemsetAsync(p_pooled, 0, NG * HID * sizeof(float));
    cudaMemsetAsync(p_counts, 0, NG * sizeof(int));

    int nb = (N + 1023) / 1024;

    // W_comb = W_proj @ W_gat ; b_comb = b_proj @ W_gat
    gemm128<<<1, 256, 131072>>>(W_proj, W_gat, nullptr, p_Wcomb, 128);
    bias_comb<<<1, 128>>>(b_proj, W_gat, p_bcomb);
    // CSR build (independent of gemm chain; stream-serialized anyway)
    hist_kernel<<<(E / 4 + 255) / 256, 256>>>(ei, p_deg, E);
    scan1<<<nb, 256>>>(p_deg, p_off, p_bsum, N);
    scan2<<<1, 64>>>(p_bsum, p_gbase, nb);
    scan3<<<nb, 256>>>(p_off, p_gbase, N, E);
    cudaMemcpyAsync(p_cursor, p_off, (size_t)N * sizeof(int), cudaMemcpyDeviceToDevice);
    scatter_kernel<<<(E / 4 + 255) / 256, 256>>>(ei, p_cursor, p_srcs, E);
    // hh = x @ W_comb + b_comb
    gemm128<<<(N + 127) / 128, 256, 131072>>>(x, p_Wcomb, p_bcomb, p_hh, N);
    attn_coef<<<(N * 4 + 255) / 256, 256>>>(p_hh, a_src, a_dst, p_esrc, p_edst, N);
    agg_fused<<<(N * 32 + 255) / 256, 256>>>(p_off, p_srcs, p_esrc, p_edst,
                                             p_hh, batch, p_pooled, p_counts, N);
    classifier<<<1, 64>>>(p_pooled, p_counts, Wc1, bc1, Wc2, bc2, (float*)d_out);
}

// round 5
// speedup vs baseline: 1.6794x; 1.0187x over previous
#include <cuda_runtime.h>
#include <cuda_fp16.h>
#include <cstdint>

#define MAX_N 50048
#define MAX_E 800000
#define HID 128
#define NG 64

// ---------------- scratch (device globals; no allocation allowed) ------------
__device__ __half2 g_hh[(size_t)MAX_N * 64];   // hh in fp16, 64 half2 per row
__device__ float g_Wcomb[HID * HID];
__device__ float g_bcomb[HID];
__device__ float g_esrc[MAX_N * 4];
__device__ float g_edst[MAX_N * 4];
__device__ int   g_deg[MAX_N];
__device__ int   g_off[MAX_N + 1];
__device__ int   g_cursor[MAX_N];
__device__ int   g_srcsort[MAX_E];
__device__ int   g_bsum[64];
__device__ int   g_gbase[64];
__device__ float g_pooled[NG * HID];
__device__ int   g_counts[NG];

// ---------------- helpers ----------------------------------------------------
__device__ __forceinline__ unsigned long long pk2(float lo, float hi) {
    unsigned long long r;
    asm("mov.b64 %0, {%1,%2};" : "=l"(r) : "f"(lo), "f"(hi));
    return r;
}
__device__ __forceinline__ void fma2(unsigned long long& d, unsigned long long a,
                                     unsigned long long b) {
    asm("fma.rn.f32x2 %0, %1, %2, %0;" : "+l"(d) : "l"(a), "l"(b));
}
__device__ __forceinline__ float2 upk(unsigned long long v) {
    float2 r;
    asm("mov.b64 {%0,%1}, %2;" : "=f"(r.x), "=f"(r.y) : "l"(v));
    return r;
}
__device__ __forceinline__ void red_add_v4(float* addr, float4 v) {
    asm volatile("red.global.add.v4.f32 [%0], {%1,%2,%3,%4};"
                 :: "l"(addr), "f"(v.x), "f"(v.y), "f"(v.z), "f"(v.w) : "memory");
}
__device__ __forceinline__ float lrelu(float x) { return x > 0.f ? x : 0.2f * x; }

// ---------------- GEMM fp32 out (for W_comb precombine) ----------------------
__global__ __launch_bounds__(256) void gemm128(const float* __restrict__ A,
                                               const float* __restrict__ W,
                                               const float* __restrict__ bias,
                                               float* __restrict__ C, int N) {
    extern __shared__ float sm[];
    float* At = sm;
    float* Ws = sm + 16384;
    const int t = threadIdx.x;
    const int row0 = blockIdx.x * 128;

    const float4* Wg = (const float4*)W;
    float4* Wsv = (float4*)Ws;
#pragma unroll
    for (int i = 0; i < 16; i++) Wsv[t + i * 256] = Wg[t + i * 256];

#pragma unroll
    for (int i = 0; i < 16; i++) {
        int idx = t + i * 256;
        int k4 = idx >> 7;
        int r  = idx & 127;
        float4 v = make_float4(0.f, 0.f, 0.f, 0.f);
        if (row0 + r < N) v = *(const float4*)(A + (size_t)(row0 + r) * 128 + k4 * 4);
        At[(k4 * 4 + 0) * 128 + r] = v.x;
        At[(k4 * 4 + 1) * 128 + r] = v.y;
        At[(k4 * 4 + 2) * 128 + r] = v.z;
        At[(k4 * 4 + 3) * 128 + r] = v.w;
    }
    __syncthreads();

    const int tx = t & 15, ty = t >> 4;
    const int cA = tx * 4, cB = tx * 4 + 64;
    const int rA = ty * 4, rB = ty * 4 + 64;

    unsigned long long acc[4][8];
#pragma unroll
    for (int i = 0; i < 4; i++)
#pragma unroll
        for (int j = 0; j < 8; j++) acc[i][j] = 0ull;

#pragma unroll 4
    for (int k = 0; k < 128; k++) {
        ulonglong2 a01 = *(const ulonglong2*)(At + k * 128 + rA);
        ulonglong2 a23 = *(const ulonglong2*)(At + k * 128 + rB);
        float4 w0 = *(const float4*)(Ws + k * 128 + cA);
        float4 w1 = *(const float4*)(Ws + k * 128 + cB);
        unsigned long long ap[4] = {a01.x, a01.y, a23.x, a23.y};
        unsigned long long wp[8] = {pk2(w0.x, w0.x), pk2(w0.y, w0.y),
                                    pk2(w0.z, w0.z), pk2(w0.w, w0.w),
                                    pk2(w1.x, w1.x), pk2(w1.y, w1.y),
                                    pk2(w1.z, w1.z), pk2(w1.w, w1.w)};
#pragma unroll
        for (int i = 0; i < 4; i++)
#pragma unroll
            for (int j = 0; j < 8; j++) fma2(acc[i][j], ap[i], wp[j]);
    }

#pragma unroll
    for (int i = 0; i < 4; i++) {
        int r0 = (i < 2) ? (rA + 2 * i) : (rB + 2 * (i - 2));
#pragma unroll
        for (int half = 0; half < 2; half++) {
            int r = r0 + half;
            if (row0 + r >= N) continue;
            float o[8];
#pragma unroll
            for (int j = 0; j < 8; j++) {
                float2 v = upk(acc[i][j]);
                o[j] = half ? v.y : v.x;
            }
            float* Cr = C + (size_t)(row0 + r) * 128;
            *(float4*)(Cr + cA) = make_float4(o[0], o[1], o[2], o[3]);
            *(float4*)(Cr + cB) = make_float4(o[4], o[5], o[6], o[7]);
        }
    }
}

// ---------------- GEMM half2 out: hh = A @ W + bias ---------------------------
__global__ __launch_bounds__(256) void gemm128h(const float* __restrict__ A,
                                                const float* __restrict__ W,
                                                const float* __restrict__ bias,
                                                __half2* __restrict__ C, int N) {
    extern __shared__ float sm[];
    float* At = sm;
    float* Ws = sm + 16384;
    const int t = threadIdx.x;
    const int row0 = blockIdx.x * 128;

    const float4* Wg = (const float4*)W;
    float4* Wsv = (float4*)Ws;
#pragma unroll
    for (int i = 0; i < 16; i++) Wsv[t + i * 256] = Wg[t + i * 256];

#pragma unroll
    for (int i = 0; i < 16; i++) {
        int idx = t + i * 256;
        int k4 = idx >> 7;
        int r  = idx & 127;
        float4 v = make_float4(0.f, 0.f, 0.f, 0.f);
        if (row0 + r < N) v = *(const float4*)(A + (size_t)(row0 + r) * 128 + k4 * 4);
        At[(k4 * 4 + 0) * 128 + r] = v.x;
        At[(k4 * 4 + 1) * 128 + r] = v.y;
        At[(k4 * 4 + 2) * 128 + r] = v.z;
        At[(k4 * 4 + 3) * 128 + r] = v.w;
    }
    __syncthreads();

    const int tx = t & 15, ty = t >> 4;
    const int cA = tx * 4, cB = tx * 4 + 64;
    const int rA = ty * 4, rB = ty * 4 + 64;

    unsigned long long acc[4][8];
#pragma unroll
    for (int i = 0; i < 4; i++)
#pragma unroll
        for (int j = 0; j < 8; j++) acc[i][j] = 0ull;

#pragma unroll 4
    for (int k = 0; k < 128; k++) {
        ulonglong2 a01 = *(const ulonglong2*)(At + k * 128 + rA);
        ulonglong2 a23 = *(const ulonglong2*)(At + k * 128 + rB);
        float4 w0 = *(const float4*)(Ws + k * 128 + cA);
        float4 w1 = *(const float4*)(Ws + k * 128 + cB);
        unsigned long long ap[4] = {a01.x, a01.y, a23.x, a23.y};
        unsigned long long wp[8] = {pk2(w0.x, w0.x), pk2(w0.y, w0.y),
                                    pk2(w0.z, w0.z), pk2(w0.w, w0.w),
                                    pk2(w1.x, w1.x), pk2(w1.y, w1.y),
                                    pk2(w1.z, w1.z), pk2(w1.w, w1.w)};
#pragma unroll
        for (int i = 0; i < 4; i++)
#pragma unroll
            for (int j = 0; j < 8; j++) fma2(acc[i][j], ap[i], wp[j]);
    }

    float4 b0 = *(const float4*)(bias + cA);
    float4 b1 = *(const float4*)(bias + cB);

#pragma unroll
    for (int i = 0; i < 4; i++) {
        int r0 = (i < 2) ? (rA + 2 * i) : (rB + 2 * (i - 2));
#pragma unroll
        for (int half = 0; half < 2; half++) {
            int r = r0 + half;
            if (row0 + r >= N) continue;
            float o[8];
#pragma unroll
            for (int j = 0; j < 8; j++) {
                float2 v = upk(acc[i][j]);
                o[j] = half ? v.y : v.x;
            }
            __half2* Cr = C + (size_t)(row0 + r) * 64;
            __half2 pa0 = __float22half2_rn(make_float2(o[0] + b0.x, o[1] + b0.y));
            __half2 pa1 = __float22half2_rn(make_float2(o[2] + b0.z, o[3] + b0.w));
            __half2 pb0 = __float22half2_rn(make_float2(o[4] + b1.x, o[5] + b1.y));
            __half2 pb1 = __float22half2_rn(make_float2(o[6] + b1.z, o[7] + b1.w));
            uint2 ua, ub;
            ua.x = *(unsigned*)&pa0; ua.y = *(unsigned*)&pa1;
            ub.x = *(unsigned*)&pb0; ub.y = *(unsigned*)&pb1;
            *(uint2*)(Cr + cA / 2) = ua;
            *(uint2*)(Cr + cB / 2) = ub;
        }
    }
}

// ---------------- combined bias: b_comb = b_proj @ W_gat ----------------------
__global__ __launch_bounds__(128) void bias_comb(const float* __restrict__ b_proj,
                                                 const float* __restrict__ W_gat,
                                                 float* __restrict__ b_comb) {
    int c = threadIdx.x;
    float s = 0.f;
#pragma unroll 8
    for (int k = 0; k < 128; k++) s += b_proj[k] * W_gat[k * 128 + c];
    b_comb[c] = s;
}

// ---------------- per-node attention coefficients (reads half hh) -------------
__global__ void attn_coef(const __half2* __restrict__ hh,
                          const float* __restrict__ a_src,
                          const float* __restrict__ a_dst,
                          float* __restrict__ esrc, float* __restrict__ edst, int N) {
    __shared__ float sa[128], sd[128];
    if (threadIdx.x < 128) { sa[threadIdx.x] = a_src[threadIdx.x]; sd[threadIdx.x] = a_dst[threadIdx.x]; }
    __syncthreads();
    int tid = blockIdx.x * blockDim.x + threadIdx.x;
    int n = tid >> 2, h = tid & 3;
    if (n >= N) return;
    const uint4* hp = (const uint4*)(hh + (size_t)n * 64 + h * 16);
    float s1 = 0.f, s2 = 0.f;
#pragma unroll
    for (int q = 0; q < 4; q++) {
        uint4 u = hp[q];
        float2 v0 = __half22float2(*(__half2*)&u.x);
        float2 v1 = __half22float2(*(__half2*)&u.y);
        float2 v2 = __half22float2(*(__half2*)&u.z);
        float2 v3 = __half22float2(*(__half2*)&u.w);
        int c = h * 32 + q * 8;
        s1 += v0.x * sa[c] + v0.y * sa[c+1] + v1.x * sa[c+2] + v1.y * sa[c+3]
            + v2.x * sa[c+4] + v2.y * sa[c+5] + v3.x * sa[c+6] + v3.y * sa[c+7];
        s2 += v0.x * sd[c] + v0.y * sd[c+1] + v1.x * sd[c+2] + v1.y * sd[c+3]
            + v2.x * sd[c+4] + v2.y * sd[c+5] + v3.x * sd[c+6] + v3.y * sd[c+7];
    }
    esrc[n * 4 + h] = s1;
    edst[n * 4 + h] = s2;
}

// ---------------- CSR build ---------------------------------------------------
__global__ void hist_kernel(const int* __restrict__ ei, int* __restrict__ deg, int E) {
    int base = (blockIdx.x * blockDim.x + threadIdx.x) * 4;
    if (base >= E) return;
#pragma unroll
    for (int j = 0; j < 4; j++) {
        int e = base + j;
        if (e < E) atomicAdd(deg + ei[E + e], 1);
    }
}

__global__ __launch_bounds__(256) void scan1(const int* __restrict__ deg,
                                             int* __restrict__ off,
                                             int* __restrict__ bsum, int N) {
    __shared__ int sc[256];
    int t = threadIdx.x;
    int base = blockIdx.x * 1024 + t * 4;
    int v[4];
#pragma unroll
    for (int j = 0; j < 4; j++) v[j] = (base + j < N) ? deg[base + j] : 0;
    int s = v[0] + v[1] + v[2] + v[3];
    sc[t] = s;
    __syncthreads();
    for (int d = 1; d < 256; d <<= 1) {
        int val = (t >= d) ? sc[t - d] : 0;
        __syncthreads();
        sc[t] += val;
        __syncthreads();
    }
    if (t == 255) bsum[blockIdx.x] = sc[255];
    int run = (t == 0) ? 0 : sc[t - 1];
#pragma unroll
    for (int j = 0; j < 4; j++) {
        if (base + j < N) off[base + j] = run;
        run += v[j];
    }
}

__global__ __launch_bounds__(64) void scan2(const int* __restrict__ bsum,
                                            int* __restrict__ gbase, int nb) {
    __shared__ int sc[64];
    int t = threadIdx.x;
    sc[t] = (t < nb) ? bsum[t] : 0;
    __syncthreads();
    for (int d = 1; d < 64; d <<= 1) {
        int val = (t >= d) ? sc[t - d] : 0;
        __syncthreads();
        sc[t] += val;
        __syncthreads();
    }
    gbase[t] = (t == 0) ? 0 : sc[t - 1];
}

// scan stage 3: add chunk bases; write off+cursor; off[N]=E
__global__ __launch_bounds__(256) void scan3(int* __restrict__ off,
                                             int* __restrict__ cursor,
                                             const int* __restrict__ gbase,
                                             int N, int E) {
    int add = gbase[blockIdx.x];
    int base = blockIdx.x * 1024 + threadIdx.x * 4;
#pragma unroll
    for (int j = 0; j < 4; j++)
        if (base + j < N) {
            int v = off[base + j] + add;
            off[base + j] = v;
            cursor[base + j] = v;
        }
    if (blockIdx.x == 0 && threadIdx.x == 0) off[N] = E;
}

__global__ void scatter_kernel(const int* __restrict__ ei, int* __restrict__ cursor,
                               int* __restrict__ srcs, int E) {
    int base = (blockIdx.x * blockDim.x + threadIdx.x) * 4;
    if (base >= E) return;
    int s[4], p[4];
#pragma unroll
    for (int j = 0; j < 4; j++) {
        int e = base + j;
        if (e < E) {
            s[j] = ei[e];
            p[j] = atomicAdd(cursor + ei[E + e], 1);
        }
    }
#pragma unroll
    for (int j = 0; j < 4; j++)
        if (base + j < E) srcs[p[j]] = s[j];
}

// ---------------- fused softmax + aggregate + pool (warp per dst node) --------
#define CAP 128
__global__ __launch_bounds__(256) void agg_fused(const int* __restrict__ off,
                                                 const int* __restrict__ srcs,
                                                 const float* __restrict__ esrc,
                                                 const float* __restrict__ edst,
                                                 const __half2* __restrict__ hh,
                                                 const int* __restrict__ batch,
                                                 float* __restrict__ pooled,
                                                 int* __restrict__ counts, int N) {
    __shared__ int    sh_src[8][CAP];
    __shared__ float4 sh_ex[8][CAP];
    int wi = threadIdx.x >> 5;
    int w = (blockIdx.x * blockDim.x + threadIdx.x) >> 5;
    int lane = threadIdx.x & 31;
    if (w >= N) return;
    int g = batch[w];
    if (lane == 0) atomicAdd(counts + g, 1);
    int beg = off[w], end = off[w + 1];
    int deg = end - beg;
    if (deg == 0) return;

    float4 b = *(const float4*)(edst + w * 4);

    // pass A: per-edge exp4 cached in smem + denominator reduction
    float4 dsum = make_float4(0.f, 0.f, 0.f, 0.f);
    for (int i = lane; i < deg; i += 32) {
        int s = srcs[beg + i];
        float4 a = *(const float4*)(esrc + s * 4);
        float4 ex = make_float4(__expf(lrelu(a.x + b.x)), __expf(lrelu(a.y + b.y)),
                                __expf(lrelu(a.z + b.z)), __expf(lrelu(a.w + b.w)));
        if (i < CAP) { sh_src[wi][i] = s; sh_ex[wi][i] = ex; }
        dsum.x += ex.x; dsum.y += ex.y; dsum.z += ex.z; dsum.w += ex.w;
    }
#pragma unroll
    for (int d = 16; d; d >>= 1) {
        dsum.x += __shfl_xor_sync(0xFFFFFFFFu, dsum.x, d);
        dsum.y += __shfl_xor_sync(0xFFFFFFFFu, dsum.y, d);
        dsum.z += __shfl_xor_sync(0xFFFFFFFFu, dsum.z, d);
        dsum.w += __shfl_xor_sync(0xFFFFFFFFu, dsum.w, d);
    }
    __syncwarp();

    int h = lane >> 3;
    float bh  = (h == 0) ? b.x : (h == 1) ? b.y : (h == 2) ? b.z : b.w;
    float dh  = (h == 0) ? dsum.x : (h == 1) ? dsum.y : (h == 2) ? dsum.z : dsum.w;
    float inv = 1.0f / dh;

    // pass B: gather half2 rows weighted by alpha; two accumulators for ILP
    float4 acc0 = make_float4(0.f, 0.f, 0.f, 0.f);
    float4 acc1 = make_float4(0.f, 0.f, 0.f, 0.f);
    int nfast = (deg < CAP) ? deg : CAP;
    int i = 0;
    for (; i + 1 < nfast; i += 2) {
        int s0 = sh_src[wi][i], s1 = sh_src[wi][i + 1];
        float4 e0 = sh_ex[wi][i], e1 = sh_ex[wi][i + 1];
        float al0 = ((h == 0) ? e0.x : (h == 1) ? e0.y : (h == 2) ? e0.z : e0.w) * inv;
        float al1 = ((h == 0) ? e1.x : (h == 1) ? e1.y : (h == 2) ? e1.z : e1.w) * inv;
        uint2 r0 = *(const uint2*)(hh + (size_t)s0 * 64 + lane * 2);
        uint2 r1 = *(const uint2*)(hh + (size_t)s1 * 64 + lane * 2);
        float2 v00 = __half22float2(*(__half2*)&r0.x);
        float2 v01 = __half22float2(*(__half2*)&r0.y);
        float2 v10 = __half22float2(*(__half2*)&r1.x);
        float2 v11 = __half22float2(*(__half2*)&r1.y);
        acc0.x += al0 * v00.x; acc0.y += al0 * v00.y;
        acc0.z += al0 * v01.x; acc0.w += al0 * v01.y;
        acc1.x += al1 * v10.x; acc1.y += al1 * v10.y;
        acc1.z += al1 * v11.x; acc1.w += al1 * v11.y;
    }
    for (; i < nfast; i++) {
        int s = sh_src[wi][i];
        float4 ex = sh_ex[wi][i];
        float alpha = ((h == 0) ? ex.x : (h == 1) ? ex.y : (h == 2) ? ex.z : ex.w) * inv;
        uint2 r = *(const uint2*)(hh + (size_t)s * 64 + lane * 2);
        float2 v0 = __half22float2(*(__half2*)&r.x);
        float2 v1 = __half22float2(*(__half2*)&r.y);
        acc0.x += alpha * v0.x; acc0.y += alpha * v0.y;
        acc0.z += alpha * v1.x; acc0.w += alpha * v1.y;
    }
    for (int j = CAP; j < deg; j++) {  // rare overflow path
        int s = srcs[beg + j];
        float alpha = __expf(lrelu(esrc[s * 4 + h] + bh)) * inv;
        uint2 r = *(const uint2*)(hh + (size_t)s * 64 + lane * 2);
        float2 v0 = __half22float2(*(__half2*)&r.x);
        float2 v1 = __half22float2(*(__half2*)&r.y);
        acc0.x += alpha * v0.x; acc0.y += alpha * v0.y;
        acc0.z += alpha * v1.x; acc0.w += alpha * v1.y;
    }
    red_add_v4(pooled + g * 128 + lane * 4,
               make_float4(acc0.x + acc1.x, acc0.y + acc1.y,
                           acc0.z + acc1.z, acc0.w + acc1.w));
}

// ---------------- classifier --------------------------------------------------
__global__ __launch_bounds__(64) void classifier(const float* __restrict__ pooled,
                                                 const int* __restrict__ counts,
                                                 const float* __restrict__ Wc1,
                                                 const float* __restrict__ bc1,
                                                 const float* __restrict__ Wc2,
                                                 const float* __restrict__ bc2,
                                                 float* __restrict__ outp) {
    __shared__ float sW1[128 * 64];
    __shared__ float sW2[128];
    __shared__ float sb1[64];
    int t = threadIdx.x;
    for (int i = t; i < 8192; i += 64) sW1[i] = Wc1[i];
    for (int i = t; i < 128; i += 64) sW2[i] = Wc2[i];
    sb1[t] = bc1[t];
    __syncthreads();

    float inv = 1.0f / fmaxf((float)counts[t], 1.0f);
    float row[128];
#pragma unroll
    for (int k = 0; k < 128; k++) row[k] = pooled[t * 128 + k] * inv;

    float o0 = bc2[0], o1 = bc2[1];
    for (int j = 0; j < 64; j++) {
        float s = sb1[j];
#pragma unroll
        for (int k = 0; k < 128; k++) s += row[k] * sW1[k * 64 + j];
        s = fmaxf(s, 0.f);
        o0 += s * sW2[j * 2];
        o1 += s * sW2[j * 2 + 1];
    }
    outp[t * 2 + 0] = o0;
    outp[t * 2 + 1] = o1;
}

// ---------------- launch ------------------------------------------------------
extern "C" void kernel_launch(void* const* d_in, const int* in_sizes, int n_in,
                              void* d_out, int out_size) {
    const float* x      = (const float*)d_in[0];
    const int*   ei     = (const int*)d_in[1];
    const int*   batch  = (const int*)d_in[2];
    const float* W_proj = (const float*)d_in[3];
    const float* b_proj = (const float*)d_in[4];
    const float* W_gat  = (const float*)d_in[5];
    const float* a_src  = (const float*)d_in[6];
    const float* a_dst  = (const float*)d_in[7];
    const float* Wc1    = (const float*)d_in[8];
    const float* bc1    = (const float*)d_in[9];
    const float* Wc2    = (const float*)d_in[10];
    const float* bc2    = (const float*)d_in[11];

    int N = in_sizes[0] / 128;
    int E = in_sizes[1] / 2;

    __half2* p_hh;
    float *p_Wcomb, *p_bcomb, *p_esrc, *p_edst, *p_pooled;
    int *p_deg, *p_off, *p_cursor, *p_srcs, *p_bsum, *p_gbase, *p_counts;
    cudaGetSymbolAddress((void**)&p_hh, g_hh);
    cudaGetSymbolAddress((void**)&p_Wcomb, g_Wcomb);
    cudaGetSymbolAddress((void**)&p_bcomb, g_bcomb);
    cudaGetSymbolAddress((void**)&p_esrc, g_esrc);
    cudaGetSymbolAddress((void**)&p_edst, g_edst);
    cudaGetSymbolAddress((void**)&p_deg, g_deg);
    cudaGetSymbolAddress((void**)&p_off, g_off);
    cudaGetSymbolAddress((void**)&p_cursor, g_cursor);
    cudaGetSymbolAddress((void**)&p_srcs, g_srcsort);
    cudaGetSymbolAddress((void**)&p_bsum, g_bsum);
    cudaGetSymbolAddress((void**)&p_gbase, g_gbase);
    cudaGetSymbolAddress((void**)&p_pooled, g_pooled);
    cudaGetSymbolAddress((void**)&p_counts, g_counts);

    cudaFuncSetAttribute(gemm128, cudaFuncAttributeMaxDynamicSharedMemorySize, 131072);
    cudaFuncSetAttribute(gemm128h, cudaFuncAttributeMaxDynamicSharedMemorySize, 131072);

    cudaMemsetAsync(p_deg, 0, (size_t)N * sizeof(int));
    cudaMemsetAsync(p_pooled, 0, NG * HID * sizeof(float));
    cudaMemsetAsync(p_counts, 0, NG * sizeof(int));

    int nb = (N + 1023) / 1024;

    // W_comb = W_proj @ W_gat ; b_comb = b_proj @ W_gat
    gemm128<<<1, 256, 131072>>>(W_proj, W_gat, nullptr, p_Wcomb, 128);
    bias_comb<<<1, 128>>>(b_proj, W_gat, p_bcomb);
    // CSR build
    hist_kernel<<<(E / 4 + 255) / 256, 256>>>(ei, p_deg, E);
    scan1<<<nb, 256>>>(p_deg, p_off, p_bsum, N);
    scan2<<<1, 64>>>(p_bsum, p_gbase, nb);
    scan3<<<nb, 256>>>(p_off, p_cursor, p_gbase, N, E);
    scatter_kernel<<<(E / 4 + 255) / 256, 256>>>(ei, p_cursor, p_srcs, E);
    // hh = x @ W_comb + b_comb  (half2 out)
    gemm128h<<<(N + 127) / 128, 256, 131072>>>(x, p_Wcomb, p_bcomb, p_hh, N);
    attn_coef<<<(N * 4 + 255) / 256, 256>>>(p_hh, a_src, a_dst, p_esrc, p_edst, N);
    agg_fused<<<(N * 32 + 255) / 256, 256>>>(p_off, p_srcs, p_esrc, p_edst,
                                             p_hh, batch, p_pooled, p_counts, N);
    classifier<<<1, 64>>>(p_pooled, p_counts, Wc1, bc1, Wc2, bc2, (float*)d_out);
}

// round 6
// speedup vs baseline: 2.1106x; 1.2568x over previous
#include <cuda_runtime.h>
#include <cuda_fp16.h>
#include <cstdint>

#define MAX_N 50048
#define MAX_E 800000
#define HID 128
#define NG 64

// ---------------- scratch (device globals; no allocation allowed) ------------
__device__ __half2 g_hh[(size_t)MAX_N * 64];
__device__ float g_Wcomb[HID * HID];
__device__ float g_bcomb[HID];
__device__ float g_esrc[MAX_N * 4];
__device__ float g_edst[MAX_N * 4];
__device__ int   g_deg[MAX_N];
__device__ int   g_off[MAX_N + 1];
__device__ int   g_cursor[MAX_N];
__device__ int   g_srcsort[MAX_E];
__device__ int   g_bsum[64];
__device__ int   g_gbase[64];
__device__ float g_pooled[NG * HID];
__device__ int   g_counts[NG];

// ---------------- helpers ----------------------------------------------------
__device__ __forceinline__ unsigned long long pk2(float lo, float hi) {
    unsigned long long r;
    asm("mov.b64 %0, {%1,%2};" : "=l"(r) : "f"(lo), "f"(hi));
    return r;
}
__device__ __forceinline__ void fma2(unsigned long long& d, unsigned long long a,
                                     unsigned long long b) {
    asm("fma.rn.f32x2 %0, %1, %2, %0;" : "+l"(d) : "l"(a), "l"(b));
}
__device__ __forceinline__ float2 upk(unsigned long long v) {
    float2 r;
    asm("mov.b64 {%0,%1}, %2;" : "=f"(r.x), "=f"(r.y) : "l"(v));
    return r;
}
__device__ __forceinline__ void red_add_v4(float* addr, float4 v) {
    asm volatile("red.global.add.v4.f32 [%0], {%1,%2,%3,%4};"
                 :: "l"(addr), "f"(v.x), "f"(v.y), "f"(v.z), "f"(v.w) : "memory");
}
__device__ __forceinline__ float lrelu(float x) { return x > 0.f ? x : 0.2f * x; }

// ---------------- parallel 128x128x128 precombine -----------------------------
// Wcomb[r][c] = sum_k Wp[r][k] * Wg[k][c]
__global__ __launch_bounds__(256) void wcomb_kernel(const float* __restrict__ Wp,
                                                    const float* __restrict__ Wg,
                                                    float* __restrict__ Wc) {
    int idx = blockIdx.x * 256 + threadIdx.x;
    int r = idx >> 7, c = idx & 127;
    float s0 = 0.f, s1 = 0.f, s2 = 0.f, s3 = 0.f;
#pragma unroll 4
    for (int k = 0; k < 128; k += 4) {
        s0 += Wp[r * 128 + k + 0] * Wg[(k + 0) * 128 + c];
        s1 += Wp[r * 128 + k + 1] * Wg[(k + 1) * 128 + c];
        s2 += Wp[r * 128 + k + 2] * Wg[(k + 2) * 128 + c];
        s3 += Wp[r * 128 + k + 3] * Wg[(k + 3) * 128 + c];
    }
    Wc[idx] = (s0 + s1) + (s2 + s3);
}

__global__ __launch_bounds__(128) void bias_comb(const float* __restrict__ b_proj,
                                                 const float* __restrict__ W_gat,
                                                 float* __restrict__ b_comb) {
    int c = threadIdx.x;
    float s = 0.f;
#pragma unroll 8
    for (int k = 0; k < 128; k++) s += b_proj[k] * W_gat[k * 128 + c];
    b_comb[c] = s;
}

// ---------------- GEMM half2 out: hh = A @ W + bias ---------------------------
__global__ __launch_bounds__(256) void gemm128h(const float* __restrict__ A,
                                                const float* __restrict__ W,
                                                const float* __restrict__ bias,
                                                __half2* __restrict__ C, int N) {
    extern __shared__ float sm[];
    float* At = sm;
    float* Ws = sm + 16384;
    const int t = threadIdx.x;
    const int row0 = blockIdx.x * 128;

    const float4* Wg = (const float4*)W;
    float4* Wsv = (float4*)Ws;
#pragma unroll
    for (int i = 0; i < 16; i++) Wsv[t + i * 256] = Wg[t + i * 256];

#pragma unroll
    for (int i = 0; i < 16; i++) {
        int idx = t + i * 256;
        int k4 = idx >> 7;
        int r  = idx & 127;
        float4 v = make_float4(0.f, 0.f, 0.f, 0.f);
        if (row0 + r < N) v = *(const float4*)(A + (size_t)(row0 + r) * 128 + k4 * 4);
        At[(k4 * 4 + 0) * 128 + r] = v.x;
        At[(k4 * 4 + 1) * 128 + r] = v.y;
        At[(k4 * 4 + 2) * 128 + r] = v.z;
        At[(k4 * 4 + 3) * 128 + r] = v.w;
    }
    __syncthreads();

    const int tx = t & 15, ty = t >> 4;
    const int cA = tx * 4, cB = tx * 4 + 64;
    const int rA = ty * 4, rB = ty * 4 + 64;

    unsigned long long acc[4][8];
#pragma unroll
    for (int i = 0; i < 4; i++)
#pragma unroll
        for (int j = 0; j < 8; j++) acc[i][j] = 0ull;

#pragma unroll 4
    for (int k = 0; k < 128; k++) {
        ulonglong2 a01 = *(const ulonglong2*)(At + k * 128 + rA);
        ulonglong2 a23 = *(const ulonglong2*)(At + k * 128 + rB);
        float4 w0 = *(const float4*)(Ws + k * 128 + cA);
        float4 w1 = *(const float4*)(Ws + k * 128 + cB);
        unsigned long long ap[4] = {a01.x, a01.y, a23.x, a23.y};
        unsigned long long wp[8] = {pk2(w0.x, w0.x), pk2(w0.y, w0.y),
                                    pk2(w0.z, w0.z), pk2(w0.w, w0.w),
                                    pk2(w1.x, w1.x), pk2(w1.y, w1.y),
                                    pk2(w1.z, w1.z), pk2(w1.w, w1.w)};
#pragma unroll
        for (int i = 0; i < 4; i++)
#pragma unroll
            for (int j = 0; j < 8; j++) fma2(acc[i][j], ap[i], wp[j]);
    }

    float4 b0 = *(const float4*)(bias + cA);
    float4 b1 = *(const float4*)(bias + cB);

#pragma unroll
    for (int i = 0; i < 4; i++) {
        int r0 = (i < 2) ? (rA + 2 * i) : (rB + 2 * (i - 2));
#pragma unroll
        for (int half = 0; half < 2; half++) {
            int r = r0 + half;
            if (row0 + r >= N) continue;
            float o[8];
#pragma unroll
            for (int j = 0; j < 8; j++) {
                float2 v = upk(acc[i][j]);
                o[j] = half ? v.y : v.x;
            }
            __half2* Cr = C + (size_t)(row0 + r) * 64;
            __half2 pa0 = __float22half2_rn(make_float2(o[0] + b0.x, o[1] + b0.y));
            __half2 pa1 = __float22half2_rn(make_float2(o[2] + b0.z, o[3] + b0.w));
            __half2 pb0 = __float22half2_rn(make_float2(o[4] + b1.x, o[5] + b1.y));
            __half2 pb1 = __float22half2_rn(make_float2(o[6] + b1.z, o[7] + b1.w));
            uint2 ua, ub;
            ua.x = *(unsigned*)&pa0; ua.y = *(unsigned*)&pa1;
            ub.x = *(unsigned*)&pb0; ub.y = *(unsigned*)&pb1;
            *(uint2*)(Cr + cA / 2) = ua;
            *(uint2*)(Cr + cB / 2) = ub;
        }
    }
}

// ---------------- per-node attention coefficients (reads half hh) -------------
__global__ void attn_coef(const __half2* __restrict__ hh,
                          const float* __restrict__ a_src,
                          const float* __restrict__ a_dst,
                          float* __restrict__ esrc, float* __restrict__ edst, int N) {
    __shared__ float sa[128], sd[128];
    if (threadIdx.x < 128) { sa[threadIdx.x] = a_src[threadIdx.x]; sd[threadIdx.x] = a_dst[threadIdx.x]; }
    __syncthreads();
    int tid = blockIdx.x * blockDim.x + threadIdx.x;
    int n = tid >> 2, h = tid & 3;
    if (n >= N) return;
    const uint4* hp = (const uint4*)(hh + (size_t)n * 64 + h * 16);
    float s1 = 0.f, s2 = 0.f;
#pragma unroll
    for (int q = 0; q < 4; q++) {
        uint4 u = hp[q];
        float2 v0 = __half22float2(*(__half2*)&u.x);
        float2 v1 = __half22float2(*(__half2*)&u.y);
        float2 v2 = __half22float2(*(__half2*)&u.z);
        float2 v3 = __half22float2(*(__half2*)&u.w);
        int c = h * 32 + q * 8;
        s1 += v0.x * sa[c] + v0.y * sa[c+1] + v1.x * sa[c+2] + v1.y * sa[c+3]
            + v2.x * sa[c+4] + v2.y * sa[c+5] + v3.x * sa[c+6] + v3.y * sa[c+7];
        s2 += v0.x * sd[c] + v0.y * sd[c+1] + v1.x * sd[c+2] + v1.y * sd[c+3]
            + v2.x * sd[c+4] + v2.y * sd[c+5] + v3.x * sd[c+6] + v3.y * sd[c+7];
    }
    esrc[n * 4 + h] = s1;
    edst[n * 4 + h] = s2;
}

// ---------------- CSR build ---------------------------------------------------
__global__ void hist_kernel(const int* __restrict__ ei, int* __restrict__ deg, int E) {
    int base = (blockIdx.x * blockDim.x + threadIdx.x) * 4;
    if (base >= E) return;
#pragma unroll
    for (int j = 0; j < 4; j++) {
        int e = base + j;
        if (e < E) atomicAdd(deg + ei[E + e], 1);
    }
}

__global__ __launch_bounds__(256) void scan1(const int* __restrict__ deg,
                                             int* __restrict__ off,
                                             int* __restrict__ bsum, int N) {
    __shared__ int sc[256];
    int t = threadIdx.x;
    int base = blockIdx.x * 1024 + t * 4;
    int v[4];
#pragma unroll
    for (int j = 0; j < 4; j++) v[j] = (base + j < N) ? deg[base + j] : 0;
    int s = v[0] + v[1] + v[2] + v[3];
    sc[t] = s;
    __syncthreads();
    for (int d = 1; d < 256; d <<= 1) {
        int val = (t >= d) ? sc[t - d] : 0;
        __syncthreads();
        sc[t] += val;
        __syncthreads();
    }
    if (t == 255) bsum[blockIdx.x] = sc[255];
    int run = (t == 0) ? 0 : sc[t - 1];
#pragma unroll
    for (int j = 0; j < 4; j++) {
        if (base + j < N) off[base + j] = run;
        run += v[j];
    }
}

__global__ __launch_bounds__(64) void scan2(const int* __restrict__ bsum,
                                            int* __restrict__ gbase, int nb) {
    __shared__ int sc[64];
    int t = threadIdx.x;
    sc[t] = (t < nb) ? bsum[t] : 0;
    __syncthreads();
    for (int d = 1; d < 64; d <<= 1) {
        int val = (t >= d) ? sc[t - d] : 0;
        __syncthreads();
        sc[t] += val;
        __syncthreads();
    }
    gbase[t] = (t == 0) ? 0 : sc[t - 1];
}

__global__ __launch_bounds__(256) void scan3(int* __restrict__ off,
                                             int* __restrict__ cursor,
                                             const int* __restrict__ gbase,
                                             int N, int E) {
    int add = gbase[blockIdx.x];
    int base = blockIdx.x * 1024 + threadIdx.x * 4;
#pragma unroll
    for (int j = 0; j < 4; j++)
        if (base + j < N) {
            int v = off[base + j] + add;
            off[base + j] = v;
            cursor[base + j] = v;
        }
    if (blockIdx.x == 0 && threadIdx.x == 0) off[N] = E;
}

__global__ void scatter_kernel(const int* __restrict__ ei, int* __restrict__ cursor,
                               int* __restrict__ srcs, int E) {
    int base = (blockIdx.x * blockDim.x + threadIdx.x) * 4;
    if (base >= E) return;
    int s[4], p[4];
#pragma unroll
    for (int j = 0; j < 4; j++) {
        int e = base + j;
        if (e < E) {
            s[j] = ei[e];
            p[j] = atomicAdd(cursor + ei[E + e], 1);
        }
    }
#pragma unroll
    for (int j = 0; j < 4; j++)
        if (base + j < E) srcs[p[j]] = s[j];
}

// ---------------- fused softmax + aggregate + pool (warp per dst node) --------
#define CAP 128
__global__ __launch_bounds__(256) void agg_fused(const int* __restrict__ off,
                                                 const int* __restrict__ srcs,
                                                 const float* __restrict__ esrc,
                                                 const float* __restrict__ edst,
                                                 const __half2* __restrict__ hh,
                                                 const int* __restrict__ batch,
                                                 float* __restrict__ pooled,
                                                 int* __restrict__ counts, int N) {
    __shared__ int    sh_src[8][CAP];
    __shared__ float4 sh_ex[8][CAP];
    int wi = threadIdx.x >> 5;
    int w = (blockIdx.x * blockDim.x + threadIdx.x) >> 5;
    int lane = threadIdx.x & 31;
    if (w >= N) return;
    int g = batch[w];
    if (lane == 0) atomicAdd(counts + g, 1);
    int beg = off[w], end = off[w + 1];
    int deg = end - beg;
    if (deg == 0) return;

    float4 b = *(const float4*)(edst + w * 4);

    float4 dsum = make_float4(0.f, 0.f, 0.f, 0.f);
    for (int i = lane; i < deg; i += 32) {
        int s = srcs[beg + i];
        float4 a = *(const float4*)(esrc + s * 4);
        float4 ex = make_float4(__expf(lrelu(a.x + b.x)), __expf(lrelu(a.y + b.y)),
                                __expf(lrelu(a.z + b.z)), __expf(lrelu(a.w + b.w)));
        if (i < CAP) { sh_src[wi][i] = s; sh_ex[wi][i] = ex; }
        dsum.x += ex.x; dsum.y += ex.y; dsum.z += ex.z; dsum.w += ex.w;
    }
#pragma unroll
    for (int d = 16; d; d >>= 1) {
        dsum.x += __shfl_xor_sync(0xFFFFFFFFu, dsum.x, d);
        dsum.y += __shfl_xor_sync(0xFFFFFFFFu, dsum.y, d);
        dsum.z += __shfl_xor_sync(0xFFFFFFFFu, dsum.z, d);
        dsum.w += __shfl_xor_sync(0xFFFFFFFFu, dsum.w, d);
    }
    __syncwarp();

    int h = lane >> 3;
    float bh  = (h == 0) ? b.x : (h == 1) ? b.y : (h == 2) ? b.z : b.w;
    float dh  = (h == 0) ? dsum.x : (h == 1) ? dsum.y : (h == 2) ? dsum.z : dsum.w;
    float inv = 1.0f / dh;

    // pass B: 4 independent load/acc chains for MLP
    float4 acc0 = make_float4(0.f, 0.f, 0.f, 0.f);
    float4 acc1 = make_float4(0.f, 0.f, 0.f, 0.f);
    float4 acc2 = make_float4(0.f, 0.f, 0.f, 0.f);
    float4 acc3 = make_float4(0.f, 0.f, 0.f, 0.f);
    int nfast = (deg < CAP) ? deg : CAP;
    int i = 0;
    for (; i + 3 < nfast; i += 4) {
        int s0 = sh_src[wi][i],     s1 = sh_src[wi][i + 1];
        int s2 = sh_src[wi][i + 2], s3 = sh_src[wi][i + 3];
        float4 e0 = sh_ex[wi][i],     e1 = sh_ex[wi][i + 1];
        float4 e2 = sh_ex[wi][i + 2], e3 = sh_ex[wi][i + 3];
        float al0 = ((h == 0) ? e0.x : (h == 1) ? e0.y : (h == 2) ? e0.z : e0.w) * inv;
        float al1 = ((h == 0) ? e1.x : (h == 1) ? e1.y : (h == 2) ? e1.z : e1.w) * inv;
        float al2 = ((h == 0) ? e2.x : (h == 1) ? e2.y : (h == 2) ? e2.z : e2.w) * inv;
        float al3 = ((h == 0) ? e3.x : (h == 1) ? e3.y : (h == 2) ? e3.z : e3.w) * inv;
        uint2 r0 = *(const uint2*)(hh + (size_t)s0 * 64 + lane * 2);
        uint2 r1 = *(const uint2*)(hh + (size_t)s1 * 64 + lane * 2);
        uint2 r2 = *(const uint2*)(hh + (size_t)s2 * 64 + lane * 2);
        uint2 r3 = *(const uint2*)(hh + (size_t)s3 * 64 + lane * 2);
        float2 a0 = __half22float2(*(__half2*)&r0.x), b0v = __half22float2(*(__half2*)&r0.y);
        float2 a1 = __half22float2(*(__half2*)&r1.x), b1v = __half22float2(*(__half2*)&r1.y);
        float2 a2 = __half22float2(*(__half2*)&r2.x), b2v = __half22float2(*(__half2*)&r2.y);
        float2 a3 = __half22float2(*(__half2*)&r3.x), b3v = __half22float2(*(__half2*)&r3.y);
        acc0.x += al0 * a0.x; acc0.y += al0 * a0.y; acc0.z += al0 * b0v.x; acc0.w += al0 * b0v.y;
        acc1.x += al1 * a1.x; acc1.y += al1 * a1.y; acc1.z += al1 * b1v.x; acc1.w += al1 * b1v.y;
        acc2.x += al2 * a2.x; acc2.y += al2 * a2.y; acc2.z += al2 * b2v.x; acc2.w += al2 * b2v.y;
        acc3.x += al3 * a3.x; acc3.y += al3 * a3.y; acc3.z += al3 * b3v.x; acc3.w += al3 * b3v.y;
    }
    for (; i < nfast; i++) {
        int s = sh_src[wi][i];
        float4 ex = sh_ex[wi][i];
        float alpha = ((h == 0) ? ex.x : (h == 1) ? ex.y : (h == 2) ? ex.z : ex.w) * inv;
        uint2 r = *(const uint2*)(hh + (size_t)s * 64 + lane * 2);
        float2 v0 = __half22float2(*(__half2*)&r.x);
        float2 v1 = __half22float2(*(__half2*)&r.y);
        acc0.x += alpha * v0.x; acc0.y += alpha * v0.y;
        acc0.z += alpha * v1.x; acc0.w += alpha * v1.y;
    }
    for (int j = CAP; j < deg; j++) {
        int s = srcs[beg + j];
        float alpha = __expf(lrelu(esrc[s * 4 + h] + bh)) * inv;
        uint2 r = *(const uint2*)(hh + (size_t)s * 64 + lane * 2);
        float2 v0 = __half22float2(*(__half2*)&r.x);
        float2 v1 = __half22float2(*(__half2*)&r.y);
        acc0.x += alpha * v0.x; acc0.y += alpha * v0.y;
        acc0.z += alpha * v1.x; acc0.w += alpha * v1.y;
    }
    red_add_v4(pooled + g * 128 + lane * 4,
               make_float4(acc0.x + acc1.x + acc2.x + acc3.x,
                           acc0.y + acc1.y + acc2.y + acc3.y,
                           acc0.z + acc1.z + acc2.z + acc3.z,
                           acc0.w + acc1.w + acc2.w + acc3.w));
}

// ---------------- classifier: warp per graph ----------------------------------
__global__ __launch_bounds__(1024) void classifier(const float* __restrict__ pooled,
                                                   const int* __restrict__ counts,
                                                   const float* __restrict__ Wc1,
                                                   const float* __restrict__ bc1,
                                                   const float* __restrict__ Wc2,
                                                   const float* __restrict__ bc2,
                                                   float* __restrict__ outp) {
    __shared__ float sW1[128 * 64];   // 32 KB
    __shared__ float srow[32][128];   // 16 KB
    int t = threadIdx.x;
    int warp = t >> 5, lane = t & 31;
    int g = blockIdx.x * 32 + warp;   // graph id
    for (int i = t; i < 8192; i += 1024) sW1[i] = Wc1[i];
    // load pooled row scaled by 1/count
    float inv = 1.0f / fmaxf((float)counts[g], 1.0f);
    float4 rv = *(const float4*)(pooled + g * 128 + lane * 4);
    srow[warp][lane * 4 + 0] = rv.x * inv;
    srow[warp][lane * 4 + 1] = rv.y * inv;
    srow[warp][lane * 4 + 2] = rv.z * inv;
    srow[warp][lane * 4 + 3] = rv.w * inv;
    __syncthreads();

    // each lane handles hidden units j0 = lane*2, j0+1
    int j0 = lane * 2;
    float s0 = bc1[j0], s1 = bc1[j0 + 1];
#pragma unroll 8
    for (int k = 0; k < 128; k++) {
        float r = srow[warp][k];
        s0 += r * sW1[k * 64 + j0];
        s1 += r * sW1[k * 64 + j0 + 1];
    }
    s0 = fmaxf(s0, 0.f);
    s1 = fmaxf(s1, 0.f);
    float o0 = s0 * Wc2[j0 * 2]     + s1 * Wc2[(j0 + 1) * 2];
    float o1 = s0 * Wc2[j0 * 2 + 1] + s1 * Wc2[(j0 + 1) * 2 + 1];
#pragma unroll
    for (int d = 16; d; d >>= 1) {
        o0 += __shfl_xor_sync(0xFFFFFFFFu, o0, d);
        o1 += __shfl_xor_sync(0xFFFFFFFFu, o1, d);
    }
    if (lane == 0) {
        outp[g * 2 + 0] = o0 + bc2[0];
        outp[g * 2 + 1] = o1 + bc2[1];
    }
}

// ---------------- launch ------------------------------------------------------
extern "C" void kernel_launch(void* const* d_in, const int* in_sizes, int n_in,
                              void* d_out, int out_size) {
    const float* x      = (const float*)d_in[0];
    const int*   ei     = (const int*)d_in[1];
    const int*   batch  = (const int*)d_in[2];
    const float* W_proj = (const float*)d_in[3];
    const float* b_proj = (const float*)d_in[4];
    const float* W_gat  = (const float*)d_in[5];
    const float* a_src  = (const float*)d_in[6];
    const float* a_dst  = (const float*)d_in[7];
    const float* Wc1    = (const float*)d_in[8];
    const float* bc1    = (const float*)d_in[9];
    const float* Wc2    = (const float*)d_in[10];
    const float* bc2    = (const float*)d_in[11];

    int N = in_sizes[0] / 128;
    int E = in_sizes[1] / 2;

    __half2* p_hh;
    float *p_Wcomb, *p_bcomb, *p_esrc, *p_edst, *p_pooled;
    int *p_deg, *p_off, *p_cursor, *p_srcs, *p_bsum, *p_gbase, *p_counts;
    cudaGetSymbolAddress((void**)&p_hh, g_hh);
    cudaGetSymbolAddress((void**)&p_Wcomb, g_Wcomb);
    cudaGetSymbolAddress((void**)&p_bcomb, g_bcomb);
    cudaGetSymbolAddress((void**)&p_esrc, g_esrc);
    cudaGetSymbolAddress((void**)&p_edst, g_edst);
    cudaGetSymbolAddress((void**)&p_deg, g_deg);
    cudaGetSymbolAddress((void**)&p_off, g_off);
    cudaGetSymbolAddress((void**)&p_cursor, g_cursor);
    cudaGetSymbolAddress((void**)&p_srcs, g_srcsort);
    cudaGetSymbolAddress((void**)&p_bsum, g_bsum);
    cudaGetSymbolAddress((void**)&p_gbase, g_gbase);
    cudaGetSymbolAddress((void**)&p_pooled, g_pooled);
    cudaGetSymbolAddress((void**)&p_counts, g_counts);

    cudaFuncSetAttribute(gemm128h, cudaFuncAttributeMaxDynamicSharedMemorySize, 131072);

    // side stream + events, fresh each call (never destroyed; a handful of
    // host-side handles over the harness's few eager calls — no device alloc)
    cudaStream_t s2;
    cudaEvent_t ev_fork, ev_join;
    cudaStreamCreateWithFlags(&s2, cudaStreamNonBlocking);
    cudaEventCreateWithFlags(&ev_fork, cudaEventDisableTiming);
    cudaEventCreateWithFlags(&ev_join, cudaEventDisableTiming);

    int nb = (N + 1023) / 1024;

    // ---- stream 0: memsets + GEMM chain
    cudaMemsetAsync(p_pooled, 0, NG * HID * sizeof(float));
    cudaMemsetAsync(p_counts, 0, NG * sizeof(int));
    cudaEventRecord(ev_fork, 0);

    // ---- side stream: CSR build (depends only on ei)
    cudaStreamWaitEvent(s2, ev_fork, 0);
    cudaMemsetAsync(p_deg, 0, (size_t)N * sizeof(int), s2);
    hist_kernel<<<(E / 4 + 255) / 256, 256, 0, s2>>>(ei, p_deg, E);
    scan1<<<nb, 256, 0, s2>>>(p_deg, p_off, p_bsum, N);
    scan2<<<1, 64, 0, s2>>>(p_bsum, p_gbase, nb);
    scan3<<<nb, 256, 0, s2>>>(p_off, p_cursor, p_gbase, N, E);
    scatter_kernel<<<(E / 4 + 255) / 256, 256, 0, s2>>>(ei, p_cursor, p_srcs, E);
    cudaEventRecord(ev_join, s2);

    // ---- stream 0 (concurrent with CSR): weights + hh + attention coefs
    wcomb_kernel<<<64, 256>>>(W_proj, W_gat, p_Wcomb);
    bias_comb<<<1, 128>>>(b_proj, W_gat, p_bcomb);
    gemm128h<<<(N + 127) / 128, 256, 131072>>>(x, p_Wcomb, p_bcomb, p_hh, N);
    attn_coef<<<(N * 4 + 255) / 256, 256>>>(p_hh, a_src, a_dst, p_esrc, p_edst, N);

    // ---- join, then aggregate + classify
    cudaStreamWaitEvent(0, ev_join, 0);
    agg_fused<<<(N * 32 + 255) / 256, 256>>>(p_off, p_srcs, p_esrc, p_edst,
                                             p_hh, batch, p_pooled, p_counts, N);
    classifier<<<2, 1024>>>(p_pooled, p_counts, Wc1, bc1, Wc2, bc2, (float*)d_out);
}

// round 7
// speedup vs baseline: 2.2179x; 1.0509x over previous
#include <cuda_runtime.h>
#include <cuda_fp16.h>
#include <cstdint>

#define MAX_N 50048
#define MAX_E 800000
#define HID 128
#define NG 64

// ---------------- scratch (device globals; no allocation allowed) ------------
__device__ __half2 g_hh[(size_t)MAX_N * 64];
__device__ float g_Wcomb[HID * HID];
__device__ float g_bcomb[HID];
__device__ float g_esrc[MAX_N * 4];
__device__ float g_edst[MAX_N * 4];
__device__ int   g_deg[MAX_N];
__device__ int   g_off[MAX_N + 1];
__device__ int   g_cursor[MAX_N];
__device__ int   g_srcsort[MAX_E];
__device__ int   g_bsum[64];
__device__ int   g_gbase[64];
__device__ float g_pooled[NG * HID];
__device__ int   g_counts[NG];

// ---------------- helpers ----------------------------------------------------
__device__ __forceinline__ unsigned long long pk2(float lo, float hi) {
    unsigned long long r;
    asm("mov.b64 %0, {%1,%2};" : "=l"(r) : "f"(lo), "f"(hi));
    return r;
}
__device__ __forceinline__ void fma2(unsigned long long& d, unsigned long long a,
                                     unsigned long long b) {
    asm("fma.rn.f32x2 %0, %1, %2, %0;" : "+l"(d) : "l"(a), "l"(b));
}
__device__ __forceinline__ float2 upk(unsigned long long v) {
    float2 r;
    asm("mov.b64 {%0,%1}, %2;" : "=f"(r.x), "=f"(r.y) : "l"(v));
    return r;
}
__device__ __forceinline__ void red_add_v4(float* addr, float4 v) {
    asm volatile("red.global.add.v4.f32 [%0], {%1,%2,%3,%4};"
                 :: "l"(addr), "f"(v.x), "f"(v.y), "f"(v.z), "f"(v.w) : "memory");
}
__device__ __forceinline__ float lrelu(float x) { return x > 0.f ? x : 0.2f * x; }

// ---------------- parallel 128x128x128 precombine -----------------------------
__global__ __launch_bounds__(256) void wcomb_kernel(const float* __restrict__ Wp,
                                                    const float* __restrict__ Wg,
                                                    float* __restrict__ Wc) {
    int idx = blockIdx.x * 256 + threadIdx.x;
    int r = idx >> 7, c = idx & 127;
    float s0 = 0.f, s1 = 0.f, s2 = 0.f, s3 = 0.f;
#pragma unroll 4
    for (int k = 0; k < 128; k += 4) {
        s0 += Wp[r * 128 + k + 0] * Wg[(k + 0) * 128 + c];
        s1 += Wp[r * 128 + k + 1] * Wg[(k + 1) * 128 + c];
        s2 += Wp[r * 128 + k + 2] * Wg[(k + 2) * 128 + c];
        s3 += Wp[r * 128 + k + 3] * Wg[(k + 3) * 128 + c];
    }
    Wc[idx] = (s0 + s1) + (s2 + s3);
}

__global__ __launch_bounds__(128) void bias_comb(const float* __restrict__ b_proj,
                                                 const float* __restrict__ W_gat,
                                                 float* __restrict__ b_comb) {
    int c = threadIdx.x;
    float s = 0.f;
#pragma unroll 8
    for (int k = 0; k < 128; k++) s += b_proj[k] * W_gat[k * 128 + c];
    b_comb[c] = s;
}

// ---------------- GEMM half2 out: hh = A @ W + bias ---------------------------
__global__ __launch_bounds__(256) void gemm128h(const float* __restrict__ A,
                                                const float* __restrict__ W,
                                                const float* __restrict__ bias,
                                                __half2* __restrict__ C, int N) {
    extern __shared__ float sm[];
    float* At = sm;
    float* Ws = sm + 16384;
    const int t = threadIdx.x;
    const int row0 = blockIdx.x * 128;

    const float4* Wg = (const float4*)W;
    float4* Wsv = (float4*)Ws;
#pragma unroll
    for (int i = 0; i < 16; i++) Wsv[t + i * 256] = Wg[t + i * 256];

#pragma unroll
    for (int i = 0; i < 16; i++) {
        int idx = t + i * 256;
        int k4 = idx >> 7;
        int r  = idx & 127;
        float4 v = make_float4(0.f, 0.f, 0.f, 0.f);
        if (row0 + r < N) v = *(const float4*)(A + (size_t)(row0 + r) * 128 + k4 * 4);
        At[(k4 * 4 + 0) * 128 + r] = v.x;
        At[(k4 * 4 + 1) * 128 + r] = v.y;
        At[(k4 * 4 + 2) * 128 + r] = v.z;
        At[(k4 * 4 + 3) * 128 + r] = v.w;
    }
    __syncthreads();

    const int tx = t & 15, ty = t >> 4;
    const int cA = tx * 4, cB = tx * 4 + 64;
    const int rA = ty * 4, rB = ty * 4 + 64;

    unsigned long long acc[4][8];
#pragma unroll
    for (int i = 0; i < 4; i++)
#pragma unroll
        for (int j = 0; j < 8; j++) acc[i][j] = 0ull;

#pragma unroll 4
    for (int k = 0; k < 128; k++) {
        ulonglong2 a01 = *(const ulonglong2*)(At + k * 128 + rA);
        ulonglong2 a23 = *(const ulonglong2*)(At + k * 128 + rB);
        float4 w0 = *(const float4*)(Ws + k * 128 + cA);
        float4 w1 = *(const float4*)(Ws + k * 128 + cB);
        unsigned long long ap[4] = {a01.x, a01.y, a23.x, a23.y};
        unsigned long long wp[8] = {pk2(w0.x, w0.x), pk2(w0.y, w0.y),
                                    pk2(w0.z, w0.z), pk2(w0.w, w0.w),
                                    pk2(w1.x, w1.x), pk2(w1.y, w1.y),
                                    pk2(w1.z, w1.z), pk2(w1.w, w1.w)};
#pragma unroll
        for (int i = 0; i < 4; i++)
#pragma unroll
            for (int j = 0; j < 8; j++) fma2(acc[i][j], ap[i], wp[j]);
    }

    float4 b0 = *(const float4*)(bias + cA);
    float4 b1 = *(const float4*)(bias + cB);

#pragma unroll
    for (int i = 0; i < 4; i++) {
        int r0 = (i < 2) ? (rA + 2 * i) : (rB + 2 * (i - 2));
#pragma unroll
        for (int half = 0; half < 2; half++) {
            int r = r0 + half;
            if (row0 + r >= N) continue;
            float o[8];
#pragma unroll
            for (int j = 0; j < 8; j++) {
                float2 v = upk(acc[i][j]);
                o[j] = half ? v.y : v.x;
            }
            __half2* Cr = C + (size_t)(row0 + r) * 64;
            __half2 pa0 = __float22half2_rn(make_float2(o[0] + b0.x, o[1] + b0.y));
            __half2 pa1 = __float22half2_rn(make_float2(o[2] + b0.z, o[3] + b0.w));
            __half2 pb0 = __float22half2_rn(make_float2(o[4] + b1.x, o[5] + b1.y));
            __half2 pb1 = __float22half2_rn(make_float2(o[6] + b1.z, o[7] + b1.w));
            uint2 ua, ub;
            ua.x = *(unsigned*)&pa0; ua.y = *(unsigned*)&pa1;
            ub.x = *(unsigned*)&pb0; ub.y = *(unsigned*)&pb1;
            *(uint2*)(Cr + cA / 2) = ua;
            *(uint2*)(Cr + cB / 2) = ub;
        }
    }
}

// ---------------- per-node attention coefficients (reads half hh) -------------
__global__ void attn_coef(const __half2* __restrict__ hh,
                          const float* __restrict__ a_src,
                          const float* __restrict__ a_dst,
                          float* __restrict__ esrc, float* __restrict__ edst, int N) {
    __shared__ float sa[128], sd[128];
    if (threadIdx.x < 128) { sa[threadIdx.x] = a_src[threadIdx.x]; sd[threadIdx.x] = a_dst[threadIdx.x]; }
    __syncthreads();
    int tid = blockIdx.x * blockDim.x + threadIdx.x;
    int n = tid >> 2, h = tid & 3;
    if (n >= N) return;
    const uint4* hp = (const uint4*)(hh + (size_t)n * 64 + h * 16);
    float s1 = 0.f, s2 = 0.f;
#pragma unroll
    for (int q = 0; q < 4; q++) {
        uint4 u = hp[q];
        float2 v0 = __half22float2(*(__half2*)&u.x);
        float2 v1 = __half22float2(*(__half2*)&u.y);
        float2 v2 = __half22float2(*(__half2*)&u.z);
        float2 v3 = __half22float2(*(__half2*)&u.w);
        int c = h * 32 + q * 8;
        s1 += v0.x * sa[c] + v0.y * sa[c+1] + v1.x * sa[c+2] + v1.y * sa[c+3]
            + v2.x * sa[c+4] + v2.y * sa[c+5] + v3.x * sa[c+6] + v3.y * sa[c+7];
        s2 += v0.x * sd[c] + v0.y * sd[c+1] + v1.x * sd[c+2] + v1.y * sd[c+3]
            + v2.x * sd[c+4] + v2.y * sd[c+5] + v3.x * sd[c+6] + v3.y * sd[c+7];
    }
    esrc[n * 4 + h] = s1;
    edst[n * 4 + h] = s2;
}

// ---------------- CSR build ---------------------------------------------------
__global__ void hist_kernel(const int* __restrict__ ei, int* __restrict__ deg, int E) {
    int base = (blockIdx.x * blockDim.x + threadIdx.x) * 4;
    if (base >= E) return;
#pragma unroll
    for (int j = 0; j < 4; j++) {
        int e = base + j;
        if (e < E) atomicAdd(deg + ei[E + e], 1);
    }
}

__global__ __launch_bounds__(256) void scan1(const int* __restrict__ deg,
                                             int* __restrict__ off,
                                             int* __restrict__ bsum, int N) {
    __shared__ int sc[256];
    int t = threadIdx.x;
    int base = blockIdx.x * 1024 + t * 4;
    int v[4];
#pragma unroll
    for (int j = 0; j < 4; j++) v[j] = (base + j < N) ? deg[base + j] : 0;
    int s = v[0] + v[1] + v[2] + v[3];
    sc[t] = s;
    __syncthreads();
    for (int d = 1; d < 256; d <<= 1) {
        int val = (t >= d) ? sc[t - d] : 0;
        __syncthreads();
        sc[t] += val;
        __syncthreads();
    }
    if (t == 255) bsum[blockIdx.x] = sc[255];
    int run = (t == 0) ? 0 : sc[t - 1];
#pragma unroll
    for (int j = 0; j < 4; j++) {
        if (base + j < N) off[base + j] = run;
        run += v[j];
    }
}

__global__ __launch_bounds__(64) void scan2(const int* __restrict__ bsum,
                                            int* __restrict__ gbase, int nb) {
    __shared__ int sc[64];
    int t = threadIdx.x;
    sc[t] = (t < nb) ? bsum[t] : 0;
    __syncthreads();
    for (int d = 1; d < 64; d <<= 1) {
        int val = (t >= d) ? sc[t - d] : 0;
        __syncthreads();
        sc[t] += val;
        __syncthreads();
    }
    gbase[t] = (t == 0) ? 0 : sc[t - 1];
}

__global__ __launch_bounds__(256) void scan3(int* __restrict__ off,
                                             int* __restrict__ cursor,
                                             const int* __restrict__ gbase,
                                             int N, int E) {
    int add = gbase[blockIdx.x];
    int base = blockIdx.x * 1024 + threadIdx.x * 4;
#pragma unroll
    for (int j = 0; j < 4; j++)
        if (base + j < N) {
            int v = off[base + j] + add;
            off[base + j] = v;
            cursor[base + j] = v;
        }
    if (blockIdx.x == 0 && threadIdx.x == 0) off[N] = E;
}

__global__ void scatter_kernel(const int* __restrict__ ei, int* __restrict__ cursor,
                               int* __restrict__ srcs, int E) {
    int base = (blockIdx.x * blockDim.x + threadIdx.x) * 4;
    if (base >= E) return;
    int s[4], p[4];
#pragma unroll
    for (int j = 0; j < 4; j++) {
        int e = base + j;
        if (e < E) {
            s[j] = ei[e];
            p[j] = atomicAdd(cursor + ei[E + e], 1);
        }
    }
#pragma unroll
    for (int j = 0; j < 4; j++)
        if (base + j < E) srcs[p[j]] = s[j];
}

// ---------------- fused softmax + aggregate + pool (warp per dst node) --------
// CAP=64: P(deg > 64) for Poisson(16) is ~1e-20; overflow path stays correct.
#define CAP 64
__global__ __launch_bounds__(256, 6) void agg_fused(const int* __restrict__ off,
                                                    const int* __restrict__ srcs,
                                                    const float* __restrict__ esrc,
                                                    const float* __restrict__ edst,
                                                    const __half2* __restrict__ hh,
                                                    const int* __restrict__ batch,
                                                    float* __restrict__ pooled,
                                                    int* __restrict__ counts, int N) {
    __shared__ int   sh_src[8][CAP];
    __shared__ float sh_al[8][4][CAP + 1];   // +1 pad: heads land in distinct banks
    int wi = threadIdx.x >> 5;
    int w = (blockIdx.x * blockDim.x + threadIdx.x) >> 5;
    int lane = threadIdx.x & 31;
    if (w >= N) return;
    int g = batch[w];
    if (lane == 0) atomicAdd(counts + g, 1);
    int beg = off[w], end = off[w + 1];
    int deg = end - beg;
    if (deg == 0) return;

    float4 b = *(const float4*)(edst + w * 4);

    // pass A: per-edge exp4 -> transposed smem + denominator reduction
    float4 dsum = make_float4(0.f, 0.f, 0.f, 0.f);
    for (int i = lane; i < deg; i += 32) {
        int s = srcs[beg + i];
        float4 a = *(const float4*)(esrc + s * 4);
        float ex0 = __expf(lrelu(a.x + b.x));
        float ex1 = __expf(lrelu(a.y + b.y));
        float ex2 = __expf(lrelu(a.z + b.z));
        float ex3 = __expf(lrelu(a.w + b.w));
        if (i < CAP) {
            sh_src[wi][i] = s;
            sh_al[wi][0][i] = ex0;
            sh_al[wi][1][i] = ex1;
            sh_al[wi][2][i] = ex2;
            sh_al[wi][3][i] = ex3;
        }
        dsum.x += ex0; dsum.y += ex1; dsum.z += ex2; dsum.w += ex3;
    }
#pragma unroll
    for (int d = 16; d; d >>= 1) {
        dsum.x += __shfl_xor_sync(0xFFFFFFFFu, dsum.x, d);
        dsum.y += __shfl_xor_sync(0xFFFFFFFFu, dsum.y, d);
        dsum.z += __shfl_xor_sync(0xFFFFFFFFu, dsum.z, d);
        dsum.w += __shfl_xor_sync(0xFFFFFFFFu, dsum.w, d);
    }
    __syncwarp();

    int h = lane >> 3;
    float bh  = (h == 0) ? b.x : (h == 1) ? b.y : (h == 2) ? b.z : b.w;
    float dh  = (h == 0) ? dsum.x : (h == 1) ? dsum.y : (h == 2) ? dsum.z : dsum.w;
    float inv = 1.0f / dh;

    const float* alp = sh_al[wi][h];
    const int*   sp  = sh_src[wi];
    const __half2* hbase = hh + lane * 2;

    // pass B: 2 independent chains; per edge: LDS.32 ×2 + LDG.64 + FMUL + 4 FFMA
    float4 acc0 = make_float4(0.f, 0.f, 0.f, 0.f);
    float4 acc1 = make_float4(0.f, 0.f, 0.f, 0.f);
    int nfast = (deg < CAP) ? deg : CAP;
    int i = 0;
    for (; i + 1 < nfast; i += 2) {
        int s0 = sp[i], s1 = sp[i + 1];
        float al0 = alp[i] * inv, al1 = alp[i + 1] * inv;
        uint2 r0 = *(const uint2*)(hbase + (size_t)s0 * 64);
        uint2 r1 = *(const uint2*)(hbase + (size_t)s1 * 64);
        float2 a0 = __half22float2(*(__half2*)&r0.x);
        float2 b0v = __half22float2(*(__half2*)&r0.y);
        float2 a1 = __half22float2(*(__half2*)&r1.x);
        float2 b1v = __half22float2(*(__half2*)&r1.y);
        acc0.x += al0 * a0.x;  acc0.y += al0 * a0.y;
        acc0.z += al0 * b0v.x; acc0.w += al0 * b0v.y;
        acc1.x += al1 * a1.x;  acc1.y += al1 * a1.y;
        acc1.z += al1 * b1v.x; acc1.w += al1 * b1v.y;
    }
    for (; i < nfast; i++) {
        int s = sp[i];
        float alpha = alp[i] * inv;
        uint2 r = *(const uint2*)(hbase + (size_t)s * 64);
        float2 v0 = __half22float2(*(__half2*)&r.x);
        float2 v1 = __half22float2(*(__half2*)&r.y);
        acc0.x += alpha * v0.x; acc0.y += alpha * v0.y;
        acc0.z += alpha * v1.x; acc0.w += alpha * v1.y;
    }
    for (int j = CAP; j < deg; j++) {  // vanishingly rare overflow path
        int s = srcs[beg + j];
        float alpha = __expf(lrelu(esrc[s * 4 + h] + bh)) * inv;
        uint2 r = *(const uint2*)(hbase + (size_t)s * 64);
        float2 v0 = __half22float2(*(__half2*)&r.x);
        float2 v1 = __half22float2(*(__half2*)&r.y);
        acc0.x += alpha * v0.x; acc0.y += alpha * v0.y;
        acc0.z += alpha * v1.x; acc0.w += alpha * v1.y;
    }
    red_add_v4(pooled + g * 128 + lane * 4,
               make_float4(acc0.x + acc1.x, acc0.y + acc1.y,
                           acc0.z + acc1.z, acc0.w + acc1.w));
}

// ---------------- classifier: warp per graph ----------------------------------
__global__ __launch_bounds__(1024) void classifier(const float* __restrict__ pooled,
                                                   const int* __restrict__ counts,
                                                   const float* __restrict__ Wc1,
                                                   const float* __restrict__ bc1,
                                                   const float* __restrict__ Wc2,
                                                   const float* __restrict__ bc2,
                                                   float* __restrict__ outp) {
    __shared__ float sW1[128 * 64];
    __shared__ float srow[32][128];
    int t = threadIdx.x;
    int warp = t >> 5, lane = t & 31;
    int g = blockIdx.x * 32 + warp;
    for (int i = t; i < 8192; i += 1024) sW1[i] = Wc1[i];
    float inv = 1.0f / fmaxf((float)counts[g], 1.0f);
    float4 rv = *(const float4*)(pooled + g * 128 + lane * 4);
    srow[warp][lane * 4 + 0] = rv.x * inv;
    srow[warp][lane * 4 + 1] = rv.y * inv;
    srow[warp][lane * 4 + 2] = rv.z * inv;
    srow[warp][lane * 4 + 3] = rv.w * inv;
    __syncthreads();

    int j0 = lane * 2;
    float s0 = bc1[j0], s1 = bc1[j0 + 1];
#pragma unroll 8
    for (int k = 0; k < 128; k++) {
        float r = srow[warp][k];
        s0 += r * sW1[k * 64 + j0];
        s1 += r * sW1[k * 64 + j0 + 1];
    }
    s0 = fmaxf(s0, 0.f);
    s1 = fmaxf(s1, 0.f);
    float o0 = s0 * Wc2[j0 * 2]     + s1 * Wc2[(j0 + 1) * 2];
    float o1 = s0 * Wc2[j0 * 2 + 1] + s1 * Wc2[(j0 + 1) * 2 + 1];
#pragma unroll
    for (int d = 16; d; d >>= 1) {
        o0 += __shfl_xor_sync(0xFFFFFFFFu, o0, d);
        o1 += __shfl_xor_sync(0xFFFFFFFFu, o1, d);
    }
    if (lane == 0) {
        outp[g * 2 + 0] = o0 + bc2[0];
        outp[g * 2 + 1] = o1 + bc2[1];
    }
}

// ---------------- launch ------------------------------------------------------
extern "C" void kernel_launch(void* const* d_in, const int* in_sizes, int n_in,
                              void* d_out, int out_size) {
    const float* x      = (const float*)d_in[0];
    const int*   ei     = (const int*)d_in[1];
    const int*   batch  = (const int*)d_in[2];
    const float* W_proj = (const float*)d_in[3];
    const float* b_proj = (const float*)d_in[4];
    const float* W_gat  = (const float*)d_in[5];
    const float* a_src  = (const float*)d_in[6];
    const float* a_dst  = (const float*)d_in[7];
    const float* Wc1    = (const float*)d_in[8];
    const float* bc1    = (const float*)d_in[9];
    const float* Wc2    = (const float*)d_in[10];
    const float* bc2    = (const float*)d_in[11];

    int N = in_sizes[0] / 128;
    int E = in_sizes[1] / 2;

    __half2* p_hh;
    float *p_Wcomb, *p_bcomb, *p_esrc, *p_edst, *p_pooled;
    int *p_deg, *p_off, *p_cursor, *p_srcs, *p_bsum, *p_gbase, *p_counts;
    cudaGetSymbolAddress((void**)&p_hh, g_hh);
    cudaGetSymbolAddress((void**)&p_Wcomb, g_Wcomb);
    cudaGetSymbolAddress((void**)&p_bcomb, g_bcomb);
    cudaGetSymbolAddress((void**)&p_esrc, g_esrc);
    cudaGetSymbolAddress((void**)&p_edst, g_edst);
    cudaGetSymbolAddress((void**)&p_deg, g_deg);
    cudaGetSymbolAddress((void**)&p_off, g_off);
    cudaGetSymbolAddress((void**)&p_cursor, g_cursor);
    cudaGetSymbolAddress((void**)&p_srcs, g_srcsort);
    cudaGetSymbolAddress((void**)&p_bsum, g_bsum);
    cudaGetSymbolAddress((void**)&p_gbase, g_gbase);
    cudaGetSymbolAddress((void**)&p_pooled, g_pooled);
    cudaGetSymbolAddress((void**)&p_counts, g_counts);

    cudaFuncSetAttribute(gemm128h, cudaFuncAttributeMaxDynamicSharedMemorySize, 131072);

    cudaStream_t s2;
    cudaEvent_t ev_fork, ev_join;
    cudaStreamCreateWithFlags(&s2, cudaStreamNonBlocking);
    cudaEventCreateWithFlags(&ev_fork, cudaEventDisableTiming);
    cudaEventCreateWithFlags(&ev_join, cudaEventDisableTiming);

    int nb = (N + 1023) / 1024;

    // ---- stream 0: memsets, then fork
    cudaMemsetAsync(p_pooled, 0, NG * HID * sizeof(float));
    cudaMemsetAsync(p_counts, 0, NG * sizeof(int));
    cudaEventRecord(ev_fork, 0);

    // ---- side stream: CSR build
    cudaStreamWaitEvent(s2, ev_fork, 0);
    cudaMemsetAsync(p_deg, 0, (size_t)N * sizeof(int), s2);
    hist_kernel<<<(E / 4 + 255) / 256, 256, 0, s2>>>(ei, p_deg, E);
    scan1<<<nb, 256, 0, s2>>>(p_deg, p_off, p_bsum, N);
    scan2<<<1, 64, 0, s2>>>(p_bsum, p_gbase, nb);
    scan3<<<nb, 256, 0, s2>>>(p_off, p_cursor, p_gbase, N, E);
    scatter_kernel<<<(E / 4 + 255) / 256, 256, 0, s2>>>(ei, p_cursor, p_srcs, E);
    cudaEventRecord(ev_join, s2);

    // ---- stream 0: weights + hh + attention coefs
    wcomb_kernel<<<64, 256>>>(W_proj, W_gat, p_Wcomb);
    bias_comb<<<1, 128>>>(b_proj, W_gat, p_bcomb);
    gemm128h<<<(N + 127) / 128, 256, 131072>>>(x, p_Wcomb, p_bcomb, p_hh, N);
    attn_coef<<<(N * 4 + 255) / 256, 256>>>(p_hh, a_src, a_dst, p_esrc, p_edst, N);

    // ---- join, aggregate, classify
    cudaStreamWaitEvent(0, ev_join, 0);
    agg_fused<<<(N * 32 + 255) / 256, 256>>>(p_off, p_srcs, p_esrc, p_edst,
                                             p_hh, batch, p_pooled, p_counts, N);
    classifier<<<2, 1024>>>(p_pooled, p_counts, Wc1, bc1, Wc2, bc2, (float*)d_out);
}

// round 9
// speedup vs baseline: 2.3339x; 1.0523x over previous
#include <cuda_runtime.h>
#include <cuda_fp16.h>
#include <cstdint>

#define MAX_N 50048
#define MAX_E 800000
#define HID 128
#define NG 64

// ---------------- scratch (device globals; no allocation allowed) ------------
__device__ __half2 g_hh[(size_t)MAX_N * 64];
__device__ float g_Wcomb[HID * HID];
__device__ float g_bcomb[HID];
__device__ float g_esrc[MAX_N * 4];
__device__ float g_edst[MAX_N * 4];
__device__ int   g_deg[MAX_N];
__device__ int   g_off[MAX_N + 1];
__device__ int   g_cursor[MAX_N];
__device__ int   g_srcsort[MAX_E];
__device__ int   g_bsum[64];
__device__ float g_pooled[NG * HID];
__device__ int   g_counts[NG];

// ---------------- helpers ----------------------------------------------------
__device__ __forceinline__ unsigned long long pk2(float lo, float hi) {
    unsigned long long r;
    asm("mov.b64 %0, {%1,%2};" : "=l"(r) : "f"(lo), "f"(hi));
    return r;
}
__device__ __forceinline__ void fma2(unsigned long long& d, unsigned long long a,
                                     unsigned long long b) {
    asm("fma.rn.f32x2 %0, %1, %2, %0;" : "+l"(d) : "l"(a), "l"(b));
}
__device__ __forceinline__ float2 upk(unsigned long long v) {
    float2 r;
    asm("mov.b64 {%0,%1}, %2;" : "=f"(r.x), "=f"(r.y) : "l"(v));
    return r;
}
__device__ __forceinline__ void red_add_v4(float* addr, float4 v) {
    asm volatile("red.global.add.v4.f32 [%0], {%1,%2,%3,%4};"
                 :: "l"(addr), "f"(v.x), "f"(v.y), "f"(v.z), "f"(v.w) : "memory");
}
__device__ __forceinline__ float lrelu(float x) { return x > 0.f ? x : 0.2f * x; }

// ---------------- parallel 128x128x128 precombine -----------------------------
__global__ __launch_bounds__(256) void wcomb_kernel(const float* __restrict__ Wp,
                                                    const float* __restrict__ Wg,
                                                    float* __restrict__ Wc) {
    int idx = blockIdx.x * 256 + threadIdx.x;
    int r = idx >> 7, c = idx & 127;
    float s0 = 0.f, s1 = 0.f, s2 = 0.f, s3 = 0.f;
#pragma unroll 4
    for (int k = 0; k < 128; k += 4) {
        s0 += Wp[r * 128 + k + 0] * Wg[(k + 0) * 128 + c];
        s1 += Wp[r * 128 + k + 1] * Wg[(k + 1) * 128 + c];
        s2 += Wp[r * 128 + k + 2] * Wg[(k + 2) * 128 + c];
        s3 += Wp[r * 128 + k + 3] * Wg[(k + 3) * 128 + c];
    }
    Wc[idx] = (s0 + s1) + (s2 + s3);
}

__global__ __launch_bounds__(128) void bias_comb(const float* __restrict__ b_proj,
                                                 const float* __restrict__ W_gat,
                                                 float* __restrict__ b_comb) {
    int c = threadIdx.x;
    float s = 0.f;
#pragma unroll 8
    for (int k = 0; k < 128; k++) s += b_proj[k] * W_gat[k * 128 + c];
    b_comb[c] = s;
}

// ---------------- GEMM half2 out: hh = A @ W + bias ---------------------------
// 8x8 per-thread tile, broadcast LDS mapping, K split into two 64 halves.
// smem: Ws 64KB ([k][c]) + At 33KB ([k][r], 132-float padded rows) -> 2 blocks/SM
#define AT_LD 132
__global__ __launch_bounds__(256, 2) void gemm128h(const float* __restrict__ A,
                                                   const float* __restrict__ W,
                                                   const float* __restrict__ bias,
                                                   __half2* __restrict__ C, int N) {
    extern __shared__ float sm[];
    float* Ws = sm;                 // 128*128
    float* At = sm + 16384;         // 64*AT_LD
    const int t = threadIdx.x;
    const int row0 = blockIdx.x * 128;

    // load full W [k][c]
    const float4* Wg = (const float4*)W;
    float4* Wsv = (float4*)Ws;
#pragma unroll
    for (int i = 0; i < 16; i++) Wsv[t + i * 256] = Wg[t + i * 256];

    const int w = t >> 5, lane = t & 31;
    const int rowb = (w >> 1) * 32;       // warp row base
    const int colb = (w & 1) * 64;        // warp col base
    const int rg = lane >> 3, cg = lane & 7;
    const int r8 = rowb + rg * 8;         // thread rows r8..r8+7
    const int c8 = colb + cg * 8;         // thread cols c8..c8+7

    unsigned long long acc[4][8];
#pragma unroll
    for (int i = 0; i < 4; i++)
#pragma unroll
        for (int j = 0; j < 8; j++) acc[i][j] = 0ull;

#pragma unroll
    for (int half = 0; half < 2; half++) {
        __syncthreads();   // protect At from previous half's readers (and W load on half 0)
        // load A columns [half*64, half*64+64) transposed into At[k][r]
#pragma unroll
        for (int i = 0; i < 8; i++) {
            int idx = t + i * 256;        // 0..2047
            int r  = idx >> 4;            // row 0..127
            int k4 = idx & 15;            // float4 within the 64-col half
            float4 v = make_float4(0.f, 0.f, 0.f, 0.f);
            if (row0 + r < N)
                v = *(const float4*)(A + (size_t)(row0 + r) * 128 + half * 64 + k4 * 4);
            At[(k4 * 4 + 0) * AT_LD + r] = v.x;
            At[(k4 * 4 + 1) * AT_LD + r] = v.y;
            At[(k4 * 4 + 2) * AT_LD + r] = v.z;
            At[(k4 * 4 + 3) * AT_LD + r] = v.w;
        }
        __syncthreads();

#pragma unroll 4
        for (int k = 0; k < 64; k++) {
            ulonglong2 a01 = *(const ulonglong2*)(At + k * AT_LD + r8);      // rows r8..r8+3
            ulonglong2 a23 = *(const ulonglong2*)(At + k * AT_LD + r8 + 4);  // rows r8+4..r8+7
            float4 w0 = *(const float4*)(Ws + (half * 64 + k) * 128 + c8);
            float4 w1 = *(const float4*)(Ws + (half * 64 + k) * 128 + c8 + 4);
            unsigned long long ap[4] = {a01.x, a01.y, a23.x, a23.y};
            unsigned long long wp[8] = {pk2(w0.x, w0.x), pk2(w0.y, w0.y),
                                        pk2(w0.z, w0.z), pk2(w0.w, w0.w),
                                        pk2(w1.x, w1.x), pk2(w1.y, w1.y),
                                        pk2(w1.z, w1.z), pk2(w1.w, w1.w)};
#pragma unroll
            for (int i = 0; i < 4; i++)
#pragma unroll
                for (int j = 0; j < 8; j++) fma2(acc[i][j], ap[i], wp[j]);
        }
    }

    float4 b0 = *(const float4*)(bias + c8);
    float4 b1 = *(const float4*)(bias + c8 + 4);
    float bb[8] = {b0.x, b0.y, b0.z, b0.w, b1.x, b1.y, b1.z, b1.w};

#pragma unroll
    for (int i = 0; i < 4; i++) {
#pragma unroll
        for (int hr = 0; hr < 2; hr++) {
            int r = r8 + 2 * i + hr;
            if (row0 + r >= N) continue;
            float o[8];
#pragma unroll
            for (int j = 0; j < 8; j++) {
                float2 v = upk(acc[i][j]);
                o[j] = hr ? v.y : v.x;
            }
            __half2 p0 = __float22half2_rn(make_float2(o[0] + bb[0], o[1] + bb[1]));
            __half2 p1 = __float22half2_rn(make_float2(o[2] + bb[2], o[3] + bb[3]));
            __half2 p2 = __float22half2_rn(make_float2(o[4] + bb[4], o[5] + bb[5]));
            __half2 p3 = __float22half2_rn(make_float2(o[6] + bb[6], o[7] + bb[7]));
            uint4 u;
            u.x = *(unsigned*)&p0; u.y = *(unsigned*)&p1;
            u.z = *(unsigned*)&p2; u.w = *(unsigned*)&p3;
            *(uint4*)(C + (size_t)(row0 + r) * 64 + c8 / 2) = u;
        }
    }
}

// ---------------- per-node attention coefficients (reads half hh) -------------
__global__ void attn_coef(const __half2* __restrict__ hh,
                          const float* __restrict__ a_src,
                          const float* __restrict__ a_dst,
                          float* __restrict__ esrc, float* __restrict__ edst, int N) {
    __shared__ float sa[128], sd[128];
    if (threadIdx.x < 128) { sa[threadIdx.x] = a_src[threadIdx.x]; sd[threadIdx.x] = a_dst[threadIdx.x]; }
    __syncthreads();
    int tid = blockIdx.x * blockDim.x + threadIdx.x;
    int n = tid >> 2, h = tid & 3;
    if (n >= N) return;
    const uint4* hp = (const uint4*)(hh + (size_t)n * 64 + h * 16);
    float s1 = 0.f, s2 = 0.f;
#pragma unroll
    for (int q = 0; q < 4; q++) {
        uint4 u = hp[q];
        float2 v0 = __half22float2(*(__half2*)&u.x);
        float2 v1 = __half22float2(*(__half2*)&u.y);
        float2 v2 = __half22float2(*(__half2*)&u.z);
        float2 v3 = __half22float2(*(__half2*)&u.w);
        int c = h * 32 + q * 8;
        s1 += v0.x * sa[c] + v0.y * sa[c+1] + v1.x * sa[c+2] + v1.y * sa[c+3]
            + v2.x * sa[c+4] + v2.y * sa[c+5] + v3.x * sa[c+6] + v3.y * sa[c+7];
        s2 += v0.x * sd[c] + v0.y * sd[c+1] + v1.x * sd[c+2] + v1.y * sd[c+3]
            + v2.x * sd[c+4] + v2.y * sd[c+5] + v3.x * sd[c+6] + v3.y * sd[c+7];
    }
    esrc[n * 4 + h] = s1;
    edst[n * 4 + h] = s2;
}

// ---------------- init: zero deg + pooled + counts in one launch --------------
__global__ void init_kernel(int* __restrict__ deg, float* __restrict__ pooled,
                            int* __restrict__ counts, int N) {
    int i = blockIdx.x * 256 + threadIdx.x;
    if (i < N) deg[i] = 0;
    if (i < NG * HID) pooled[i] = 0.f;
    if (i < NG) counts[i] = 0;
}

// ---------------- CSR build ---------------------------------------------------
// histogram: 16 edges/thread, fire-and-forget REDs
__global__ void hist_kernel(const int* __restrict__ ei, int* __restrict__ deg, int E) {
    int base = (blockIdx.x * blockDim.x + threadIdx.x) * 16;
    if (base >= E) return;
    if (base + 16 <= E) {
        const int4* p = (const int4*)(ei + E + base);
#pragma unroll
        for (int q = 0; q < 4; q++) {
            int4 d = p[q];
            atomicAdd(deg + d.x, 1);
            atomicAdd(deg + d.y, 1);
            atomicAdd(deg + d.z, 1);
            atomicAdd(deg + d.w, 1);
        }
    } else {
        for (int e = base; e < E; e++) atomicAdd(deg + ei[E + e], 1);
    }
}

__global__ __launch_bounds__(256) void scan1(const int* __restrict__ deg,
                                             int* __restrict__ off,
                                             int* __restrict__ bsum, int N) {
    __shared__ int sc[256];
    int t = threadIdx.x;
    int base = blockIdx.x * 1024 + t * 4;
    int v[4];
#pragma unroll
    for (int j = 0; j < 4; j++) v[j] = (base + j < N) ? deg[base + j] : 0;
    int s = v[0] + v[1] + v[2] + v[3];
    sc[t] = s;
    __syncthreads();
    for (int d = 1; d < 256; d <<= 1) {
        int val = (t >= d) ? sc[t - d] : 0;
        __syncthreads();
        sc[t] += val;
        __syncthreads();
    }
    if (t == 255) bsum[blockIdx.x] = sc[255];
    int run = (t == 0) ? 0 : sc[t - 1];
#pragma unroll
    for (int j = 0; j < 4; j++) {
        if (base + j < N) off[base + j] = run;
        run += v[j];
    }
}

// scan3: each block computes its own prefix of bsum (scan2 folded in)
__global__ __launch_bounds__(256) void scan3(int* __restrict__ off,
                                             int* __restrict__ cursor,
                                             const int* __restrict__ bsum,
                                             int N, int E, int nb) {
    __shared__ int sb[64];
    __shared__ int s_add;
    int t = threadIdx.x;
    if (t < 64) sb[t] = (t < nb && t < blockIdx.x) ? bsum[t] : 0;
    __syncthreads();
    if (t == 0) {
        int s = 0;
#pragma unroll 8
        for (int i = 0; i < 64; i++) s += sb[i];
        s_add = s;
    }
    __syncthreads();
    int add = s_add;
    int base = blockIdx.x * 1024 + t * 4;
#pragma unroll
    for (int j = 0; j < 4; j++)
        if (base + j < N) {
            int v = off[base + j] + add;
            off[base + j] = v;
            cursor[base + j] = v;
        }
    if (blockIdx.x == 0 && t == 0) off[N] = E;
}

// scatter: 8 edges/thread with cursor atomics
__global__ void scatter_kernel(const int* __restrict__ ei, int* __restrict__ cursor,
                               int* __restrict__ srcs, int E) {
    int base = (blockIdx.x * blockDim.x + threadIdx.x) * 8;
    if (base >= E) return;
    if (base + 8 <= E) {
        int s[8], p[8];
        const int4* ps = (const int4*)(ei + base);
        const int4* pd = (const int4*)(ei + E + base);
        int4 s0 = ps[0], s1 = ps[1];
        int4 d0 = pd[0], d1 = pd[1];
        s[0] = s0.x; s[1] = s0.y; s[2] = s0.z; s[3] = s0.w;
        s[4] = s1.x; s[5] = s1.y; s[6] = s1.z; s[7] = s1.w;
        p[0] = atomicAdd(cursor + d0.x, 1);
        p[1] = atomicAdd(cursor + d0.y, 1);
        p[2] = atomicAdd(cursor + d0.z, 1);
        p[3] = atomicAdd(cursor + d0.w, 1);
        p[4] = atomicAdd(cursor + d1.x, 1);
        p[5] = atomicAdd(cursor + d1.y, 1);
        p[6] = atomicAdd(cursor + d1.z, 1);
        p[7] = atomicAdd(cursor + d1.w, 1);
#pragma unroll
        for (int j = 0; j < 8; j++) srcs[p[j]] = s[j];
    } else {
        for (int e = base; e < E; e++) {
            int sv = ei[e];
            int pv = atomicAdd(cursor + ei[E + e], 1);
            srcs[pv] = sv;
        }
    }
}

// ---------------- fused softmax + aggregate + pool (warp per dst node) --------
#define CAP 64
__global__ __launch_bounds__(256, 6) void agg_fused(const int* __restrict__ off,
                                                    const int* __restrict__ srcs,
                                                    const float* __restrict__ esrc,
                                                    const float* __restrict__ edst,
                                                    const __half2* __restrict__ hh,
                                                    const int* __restrict__ batch,
                                                    float* __restrict__ pooled,
                                                    int* __restrict__ counts, int N) {
    __shared__ int   sh_src[8][CAP];
    __shared__ float sh_al[8][4][CAP + 1];
    int wi = threadIdx.x >> 5;
    int w = (blockIdx.x * blockDim.x + threadIdx.x) >> 5;
    int lane = threadIdx.x & 31;
    if (w >= N) return;
    int g = batch[w];
    if (lane == 0) atomicAdd(counts + g, 1);
    int beg = off[w], end = off[w + 1];
    int deg = end - beg;
    if (deg == 0) return;

    float4 b = *(const float4*)(edst + w * 4);

    float4 dsum = make_float4(0.f, 0.f, 0.f, 0.f);
    for (int i = lane; i < deg; i += 32) {
        int s = srcs[beg + i];
        float4 a = *(const float4*)(esrc + s * 4);
        float ex0 = __expf(lrelu(a.x + b.x));
        float ex1 = __expf(lrelu(a.y + b.y));
        float ex2 = __expf(lrelu(a.z + b.z));
        float ex3 = __expf(lrelu(a.w + b.w));
        if (i < CAP) {
            sh_src[wi][i] = s;
            sh_al[wi][0][i] = ex0;
            sh_al[wi][1][i] = ex1;
            sh_al[wi][2][i] = ex2;
            sh_al[wi][3][i] = ex3;
        }
        dsum.x += ex0; dsum.y += ex1; dsum.z += ex2; dsum.w += ex3;
    }
#pragma unroll
    for (int d = 16; d; d >>= 1) {
        dsum.x += __shfl_xor_sync(0xFFFFFFFFu, dsum.x, d);
        dsum.y += __shfl_xor_sync(0xFFFFFFFFu, dsum.y, d);
        dsum.z += __shfl_xor_sync(0xFFFFFFFFu, dsum.z, d);
        dsum.w += __shfl_xor_sync(0xFFFFFFFFu, dsum.w, d);
    }
    __syncwarp();

    int h = lane >> 3;
    float bh  = (h == 0) ? b.x : (h == 1) ? b.y : (h == 2) ? b.z : b.w;
    float dh  = (h == 0) ? dsum.x : (h == 1) ? dsum.y : (h == 2) ? dsum.z : dsum.w;
    float inv = 1.0f / dh;

    const float* alp = sh_al[wi][h];
    const int*   sp  = sh_src[wi];
    const __half2* hbase = hh + lane * 2;

    float4 acc0 = make_float4(0.f, 0.f, 0.f, 0.f);
    float4 acc1 = make_float4(0.f, 0.f, 0.f, 0.f);
    int nfast = (deg < CAP) ? deg : CAP;
    int i = 0;
    for (; i + 1 < nfast; i += 2) {
        int s0 = sp[i], s1 = sp[i + 1];
        float al0 = alp[i] * inv, al1 = alp[i + 1] * inv;
        uint2 r0 = *(const uint2*)(hbase + (size_t)s0 * 64);
        uint2 r1 = *(const uint2*)(hbase + (size_t)s1 * 64);
        float2 a0 = __half22float2(*(__half2*)&r0.x);
        float2 b0v = __half22float2(*(__half2*)&r0.y);
        float2 a1 = __half22float2(*(__half2*)&r1.x);
        float2 b1v = __half22float2(*(__half2*)&r1.y);
        acc0.x += al0 * a0.x;  acc0.y += al0 * a0.y;
        acc0.z += al0 * b0v.x; acc0.w += al0 * b0v.y;
        acc1.x += al1 * a1.x;  acc1.y += al1 * a1.y;
        acc1.z += al1 * b1v.x; acc1.w += al1 * b1v.y;
    }
    for (; i < nfast; i++) {
        int s = sp[i];
        float alpha = alp[i] * inv;
        uint2 r = *(const uint2*)(hbase + (size_t)s * 64);
        float2 v0 = __half22float2(*(__half2*)&r.x);
        float2 v1 = __half22float2(*(__half2*)&r.y);
        acc0.x += alpha * v0.x; acc0.y += alpha * v0.y;
        acc0.z += alpha * v1.x; acc0.w += alpha * v1.y;
    }
    for (int j = CAP; j < deg; j++) {
        int s = srcs[beg + j];
        float alpha = __expf(lrelu(esrc[s * 4 + h] + bh)) * inv;
        uint2 r = *(const uint2*)(hbase + (size_t)s * 64);
        float2 v0 = __half22float2(*(__half2*)&r.x);
        float2 v1 = __half22float2(*(__half2*)&r.y);
        acc0.x += alpha * v0.x; acc0.y += alpha * v0.y;
        acc0.z += alpha * v1.x; acc0.w += alpha * v1.y;
    }
    red_add_v4(pooled + g * 128 + lane * 4,
               make_float4(acc0.x + acc1.x, acc0.y + acc1.y,
                           acc0.z + acc1.z, acc0.w + acc1.w));
}

// ---------------- classifier: warp per graph ----------------------------------
__global__ __launch_bounds__(1024) void classifier(const float* __restrict__ pooled,
                                                   const int* __restrict__ counts,
                                                   const float* __restrict__ Wc1,
                                                   const float* __restrict__ bc1,
                                                   const float* __restrict__ Wc2,
                                                   const float* __restrict__ bc2,
                                                   float* __restrict__ outp) {
    __shared__ float sW1[128 * 64];
    __shared__ float srow[32][128];
    int t = threadIdx.x;
    int warp = t >> 5, lane = t & 31;
    int g = blockIdx.x * 32 + warp;
    for (int i = t; i < 8192; i += 1024) sW1[i] = Wc1[i];
    float inv = 1.0f / fmaxf((float)counts[g], 1.0f);
    float4 rv = *(const float4*)(pooled + g * 128 + lane * 4);
    srow[warp][lane * 4 + 0] = rv.x * inv;
    srow[warp][lane * 4 + 1] = rv.y * inv;
    srow[warp][lane * 4 + 2] = rv.z * inv;
    srow[warp][lane * 4 + 3] = rv.w * inv;
    __syncthreads();

    int j0 = lane * 2;
    float s0 = bc1[j0], s1 = bc1[j0 + 1];
#pragma unroll 8
    for (int k = 0; k < 128; k++) {
        float r = srow[warp][k];
        s0 += r * sW1[k * 64 + j0];
        s1 += r * sW1[k * 64 + j0 + 1];
    }
    s0 = fmaxf(s0, 0.f);
    s1 = fmaxf(s1, 0.f);
    float o0 = s0 * Wc2[j0 * 2]     + s1 * Wc2[(j0 + 1) * 2];
    float o1 = s0 * Wc2[j0 * 2 + 1] + s1 * Wc2[(j0 + 1) * 2 + 1];
#pragma unroll
    for (int d = 16; d; d >>= 1) {
        o0 += __shfl_xor_sync(0xFFFFFFFFu, o0, d);
        o1 += __shfl_xor_sync(0xFFFFFFFFu, o1, d);
    }
    if (lane == 0) {
        outp[g * 2 + 0] = o0 + bc2[0];
        outp[g * 2 + 1] = o1 + bc2[1];
    }
}

// ---------------- launch ------------------------------------------------------
extern "C" void kernel_launch(void* const* d_in, const int* in_sizes, int n_in,
                              void* d_out, int out_size) {
    const float* x      = (const float*)d_in[0];
    const int*   ei     = (const int*)d_in[1];
    const int*   batch  = (const int*)d_in[2];
    const float* W_proj = (const float*)d_in[3];
    const float* b_proj = (const float*)d_in[4];
    const float* W_gat  = (const float*)d_in[5];
    const float* a_src  = (const float*)d_in[6];
    const float* a_dst  = (const float*)d_in[7];
    const float* Wc1    = (const float*)d_in[8];
    const float* bc1    = (const float*)d_in[9];
    const float* Wc2    = (const float*)d_in[10];
    const float* bc2    = (const float*)d_in[11];

    int N = in_sizes[0] / 128;
    int E = in_sizes[1] / 2;

    __half2* p_hh;
    float *p_Wcomb, *p_bcomb, *p_esrc, *p_edst, *p_pooled;
    int *p_deg, *p_off, *p_cursor, *p_srcs, *p_bsum, *p_counts;
    cudaGetSymbolAddress((void**)&p_hh, g_hh);
    cudaGetSymbolAddress((void**)&p_Wcomb, g_Wcomb);
    cudaGetSymbolAddress((void**)&p_bcomb, g_bcomb);
    cudaGetSymbolAddress((void**)&p_esrc, g_esrc);
    cudaGetSymbolAddress((void**)&p_edst, g_edst);
    cudaGetSymbolAddress((void**)&p_deg, g_deg);
    cudaGetSymbolAddress((void**)&p_off, g_off);
    cudaGetSymbolAddress((void**)&p_cursor, g_cursor);
    cudaGetSymbolAddress((void**)&p_srcs, g_srcsort);
    cudaGetSymbolAddress((void**)&p_bsum, g_bsum);
    cudaGetSymbolAddress((void**)&p_pooled, g_pooled);
    cudaGetSymbolAddress((void**)&p_counts, g_counts);

    const int GEMM_SMEM = (16384 + 64 * AT_LD) * 4;   // Ws + At bytes
    cudaFuncSetAttribute(gemm128h, cudaFuncAttributeMaxDynamicSharedMemorySize, GEMM_SMEM);

    cudaStream_t s2;
    cudaEvent_t ev_fork, ev_join;
    cudaStreamCreateWithFlags(&s2, cudaStreamNonBlocking);
    cudaEventCreateWithFlags(&ev_fork, cudaEventDisableTiming);
    cudaEventCreateWithFlags(&ev_join, cudaEventDisableTiming);

    int nb = (N + 1023) / 1024;

    // ---- stream 0: single init kernel, then fork
    init_kernel<<<(N + 255) / 256, 256>>>(p_deg, p_pooled, p_counts, N);
    cudaEventRecord(ev_fork, 0);

    // ---- side stream: CSR build
    cudaStreamWaitEvent(s2, ev_fork, 0);
    hist_kernel<<<(E / 16 + 255) / 256, 256, 0, s2>>>(ei, p_deg, E);
    scan1<<<nb, 256, 0, s2>>>(p_deg, p_off, p_bsum, N);
    scan3<<<nb, 256, 0, s2>>>(p_off, p_cursor, p_bsum, N, E, nb);
    scatter_kernel<<<(E / 8 + 255) / 256, 256, 0, s2>>>(ei, p_cursor, p_srcs, E);
    cudaEventRecord(ev_join, s2);

    // ---- stream 0: weights + hh + attention coefs
    wcomb_kernel<<<64, 256>>>(W_proj, W_gat, p_Wcomb);
    bias_comb<<<1, 128>>>(b_proj, W_gat, p_bcomb);
    gemm128h<<<(N + 127) / 128, 256, GEMM_SMEM>>>(x, p_Wcomb, p_bcomb, p_hh, N);
    attn_coef<<<(N * 4 + 255) / 256, 256>>>(p_hh, a_src, a_dst, p_esrc, p_edst, N);

    // ---- join, aggregate, classify
    cudaStreamWaitEvent(0, ev_join, 0);
    agg_fused<<<(N * 32 + 255) / 256, 256>>>(p_off, p_srcs, p_esrc, p_edst,
                                             p_hh, batch, p_pooled, p_counts, N);
    classifier<<<2, 1024>>>(p_pooled, p_counts, Wc1, bc1, Wc2, bc2, (float*)d_out);
}

// round 10
// speedup vs baseline: 2.5725x; 1.1022x over previous
#include <cuda_runtime.h>
#include <cuda_fp16.h>
#include <cstdint>

#define MAX_N 50048
#define MAX_E 800000
#define HID 128
#define NG 64

// ---------------- scratch (device globals; no allocation allowed) ------------
__device__ __half2 g_hh[(size_t)MAX_N * 64];
__device__ float g_Wcomb[HID * HID];
__device__ float g_bcomb[HID];
__device__ float g_esrc[MAX_N * 4];
__device__ float g_edst[MAX_N * 4];
__device__ int   g_deg[MAX_N];
__device__ int   g_off[MAX_N + 1];
__device__ int   g_cursor[MAX_N];
__device__ int   g_srcsort[MAX_E];
__device__ int   g_flag[64];
__device__ int   g_agg[64];
__device__ float g_pooled[NG * HID];

// ---------------- helpers ----------------------------------------------------
__device__ __forceinline__ unsigned long long pk2(float lo, float hi) {
    unsigned long long r;
    asm("mov.b64 %0, {%1,%2};" : "=l"(r) : "f"(lo), "f"(hi));
    return r;
}
__device__ __forceinline__ void fma2(unsigned long long& d, unsigned long long a,
                                     unsigned long long b) {
    asm("fma.rn.f32x2 %0, %1, %2, %0;" : "+l"(d) : "l"(a), "l"(b));
}
__device__ __forceinline__ float2 upk(unsigned long long v) {
    float2 r;
    asm("mov.b64 {%0,%1}, %2;" : "=f"(r.x), "=f"(r.y) : "l"(v));
    return r;
}
__device__ __forceinline__ void red_add_v4(float* addr, float4 v) {
    asm volatile("red.global.add.v4.f32 [%0], {%1,%2,%3,%4};"
                 :: "l"(addr), "f"(v.x), "f"(v.y), "f"(v.z), "f"(v.w) : "memory");
}
__device__ __forceinline__ float lrelu(float x) { return x > 0.f ? x : 0.2f * x; }

// ---------------- init: zero deg + pooled + scan flags ------------------------
__global__ void init_kernel(int* __restrict__ deg, float* __restrict__ pooled,
                            int* __restrict__ flags, int N) {
    int i = blockIdx.x * 256 + threadIdx.x;
    if (i < N) deg[i] = 0;
    if (i < NG * HID) pooled[i] = 0.f;
    if (i < 64) flags[i] = 0;
}

// ---------------- Wcomb = Wp @ Wg (blocks 0..63) ; bcomb (block 64) -----------
__global__ __launch_bounds__(256) void wcomb_bias(const float* __restrict__ Wp,
                                                  const float* __restrict__ Wg,
                                                  const float* __restrict__ bp,
                                                  float* __restrict__ Wc,
                                                  float* __restrict__ bc) {
    if (blockIdx.x < 64) {
        int idx = blockIdx.x * 256 + threadIdx.x;
        int r = idx >> 7, c = idx & 127;
        float s0 = 0.f, s1 = 0.f, s2 = 0.f, s3 = 0.f;
#pragma unroll 4
        for (int k = 0; k < 128; k += 4) {
            s0 += Wp[r * 128 + k + 0] * Wg[(k + 0) * 128 + c];
            s1 += Wp[r * 128 + k + 1] * Wg[(k + 1) * 128 + c];
            s2 += Wp[r * 128 + k + 2] * Wg[(k + 2) * 128 + c];
            s3 += Wp[r * 128 + k + 3] * Wg[(k + 3) * 128 + c];
        }
        Wc[idx] = (s0 + s1) + (s2 + s3);
    } else if (threadIdx.x < 128) {
        int c = threadIdx.x;
        float s = 0.f;
#pragma unroll 8
        for (int k = 0; k < 128; k++) s += bp[k] * Wg[k * 128 + c];
        bc[c] = s;
    }
}

// ---------------- GEMM half2 out + fused attention coefficients ---------------
// 8x8 per-thread tile. Head h = cols [h*32, h*32+32) lies inside one 4-lane
// shfl group -> esrc/edst computed in-register, no separate attn kernel.
#define AT_LD 132
__global__ __launch_bounds__(256, 2) void gemm128h(const float* __restrict__ A,
                                                   const float* __restrict__ W,
                                                   const float* __restrict__ bias,
                                                   const float* __restrict__ a_src,
                                                   const float* __restrict__ a_dst,
                                                   __half2* __restrict__ C,
                                                   float* __restrict__ esrc,
                                                   float* __restrict__ edst, int N) {
    extern __shared__ float sm[];
    float* Ws = sm;                 // 128*128
    float* At = sm + 16384;         // 64*AT_LD
    const int t = threadIdx.x;
    const int row0 = blockIdx.x * 128;

    const float4* Wg = (const float4*)W;
    float4* Wsv = (float4*)Ws;
#pragma unroll
    for (int i = 0; i < 16; i++) Wsv[t + i * 256] = Wg[t + i * 256];

    const int w = t >> 5, lane = t & 31;
    const int rowb = (w >> 1) * 32;
    const int colb = (w & 1) * 64;
    const int rg = lane >> 3, cg = lane & 7;
    const int r8 = rowb + rg * 8;
    const int c8 = colb + cg * 8;

    unsigned long long acc[4][8];
#pragma unroll
    for (int i = 0; i < 4; i++)
#pragma unroll
        for (int j = 0; j < 8; j++) acc[i][j] = 0ull;

#pragma unroll
    for (int half = 0; half < 2; half++) {
        __syncthreads();
#pragma unroll
        for (int i = 0; i < 8; i++) {
            int idx = t + i * 256;
            int r  = idx >> 4;
            int k4 = idx & 15;
            float4 v = make_float4(0.f, 0.f, 0.f, 0.f);
            if (row0 + r < N)
                v = *(const float4*)(A + (size_t)(row0 + r) * 128 + half * 64 + k4 * 4);
            At[(k4 * 4 + 0) * AT_LD + r] = v.x;
            At[(k4 * 4 + 1) * AT_LD + r] = v.y;
            At[(k4 * 4 + 2) * AT_LD + r] = v.z;
            At[(k4 * 4 + 3) * AT_LD + r] = v.w;
        }
        __syncthreads();

#pragma unroll 4
        for (int k = 0; k < 64; k++) {
            ulonglong2 a01 = *(const ulonglong2*)(At + k * AT_LD + r8);
            ulonglong2 a23 = *(const ulonglong2*)(At + k * AT_LD + r8 + 4);
            float4 w0 = *(const float4*)(Ws + (half * 64 + k) * 128 + c8);
            float4 w1 = *(const float4*)(Ws + (half * 64 + k) * 128 + c8 + 4);
            unsigned long long ap[4] = {a01.x, a01.y, a23.x, a23.y};
            unsigned long long wp[8] = {pk2(w0.x, w0.x), pk2(w0.y, w0.y),
                                        pk2(w0.z, w0.z), pk2(w0.w, w0.w),
                                        pk2(w1.x, w1.x), pk2(w1.y, w1.y),
                                        pk2(w1.z, w1.z), pk2(w1.w, w1.w)};
#pragma unroll
            for (int i = 0; i < 4; i++)
#pragma unroll
                for (int j = 0; j < 8; j++) fma2(acc[i][j], ap[i], wp[j]);
        }
    }

    float4 b0 = *(const float4*)(bias + c8);
    float4 b1 = *(const float4*)(bias + c8 + 4);
    float bb[8] = {b0.x, b0.y, b0.z, b0.w, b1.x, b1.y, b1.z, b1.w};
    float4 as0 = *(const float4*)(a_src + c8);
    float4 as1 = *(const float4*)(a_src + c8 + 4);
    float4 ad0 = *(const float4*)(a_dst + c8);
    float4 ad1 = *(const float4*)(a_dst + c8 + 4);
    float sa8[8] = {as0.x, as0.y, as0.z, as0.w, as1.x, as1.y, as1.z, as1.w};
    float sd8[8] = {ad0.x, ad0.y, ad0.z, ad0.w, ad1.x, ad1.y, ad1.z, ad1.w};
    const int head = c8 >> 5;

#pragma unroll
    for (int i = 0; i < 4; i++) {
#pragma unroll
        for (int hr = 0; hr < 2; hr++) {
            int r = r8 + 2 * i + hr;
            bool ok = (row0 + r < N);
            float v[8];
#pragma unroll
            for (int j = 0; j < 8; j++) {
                float2 p = upk(acc[i][j]);
                v[j] = (hr ? p.y : p.x) + bb[j];
            }
            // hh store (fp16)
            if (ok) {
                __half2 p0 = __float22half2_rn(make_float2(v[0], v[1]));
                __half2 p1 = __float22half2_rn(make_float2(v[2], v[3]));
                __half2 p2 = __float22half2_rn(make_float2(v[4], v[5]));
                __half2 p3 = __float22half2_rn(make_float2(v[6], v[7]));
                uint4 u;
                u.x = *(unsigned*)&p0; u.y = *(unsigned*)&p1;
                u.z = *(unsigned*)&p2; u.w = *(unsigned*)&p3;
                *(uint4*)(C + (size_t)(row0 + r) * 64 + c8 / 2) = u;
            }
            // per-head attention partials; 4-lane shfl reduce (unconditional)
            float ps = 0.f, pd = 0.f;
#pragma unroll
            for (int j = 0; j < 8; j++) { ps += v[j] * sa8[j]; pd += v[j] * sd8[j]; }
            ps += __shfl_xor_sync(0xFFFFFFFFu, ps, 1);
            pd += __shfl_xor_sync(0xFFFFFFFFu, pd, 1);
            ps += __shfl_xor_sync(0xFFFFFFFFu, ps, 2);
            pd += __shfl_xor_sync(0xFFFFFFFFu, pd, 2);
            if (ok && (lane & 3) == 0) {
                esrc[(row0 + r) * 4 + head] = ps;
                edst[(row0 + r) * 4 + head] = pd;
            }
        }
    }
}

// ---------------- CSR build ---------------------------------------------------
__global__ void hist_kernel(const int* __restrict__ ei, int* __restrict__ deg, int E) {
    int base = (blockIdx.x * blockDim.x + threadIdx.x) * 16;
    if (base >= E) return;
    if (base + 16 <= E) {
        const int4* p = (const int4*)(ei + E + base);
#pragma unroll
        for (int q = 0; q < 4; q++) {
            int4 d = p[q];
            atomicAdd(deg + d.x, 1);
            atomicAdd(deg + d.y, 1);
            atomicAdd(deg + d.z, 1);
            atomicAdd(deg + d.w, 1);
        }
    } else {
        for (int e = base; e < E; e++) atomicAdd(deg + ei[E + e], 1);
    }
}

// single-pass exclusive scan with decoupled lookback (<=64 blocks, all resident)
__global__ __launch_bounds__(256) void scan_fused(const int* __restrict__ deg,
                                                  int* __restrict__ off,
                                                  int* __restrict__ cursor,
                                                  volatile int* __restrict__ flags,
                                                  int* __restrict__ aggs,
                                                  int N, int E) {
    __shared__ int sc[256];
    __shared__ int s_pred[64];
    __shared__ int s_add;
    int t = threadIdx.x, bid = blockIdx.x;
    int base = bid * 1024 + t * 4;
    int v[4];
#pragma unroll
    for (int j = 0; j < 4; j++) v[j] = (base + j < N) ? deg[base + j] : 0;
    int s = v[0] + v[1] + v[2] + v[3];
    sc[t] = s;
    __syncthreads();
    for (int d = 1; d < 256; d <<= 1) {
        int val = (t >= d) ? sc[t - d] : 0;
        __syncthreads();
        sc[t] += val;
        __syncthreads();
    }
    if (t == 0) {
        aggs[bid] = sc[255];
        __threadfence();
        flags[bid] = 1;
    }
    if (t < 64) {
        int p = 0;
        if (t < bid) {
            while (flags[t] == 0) { }
            p = aggs[t];
        }
        s_pred[t] = p;
    }
    __syncthreads();
    if (t == 0) {
        int a = 0;
#pragma unroll 8
        for (int i = 0; i < 64; i++) a += s_pred[i];
        s_add = a;
    }
    __syncthreads();
    int add = s_add;
    int run = add + ((t == 0) ? 0 : sc[t - 1]);
#pragma unroll
    for (int j = 0; j < 4; j++) {
        if (base + j < N) { off[base + j] = run; cursor[base + j] = run; }
        run += v[j];
    }
    if (bid == 0 && t == 0) off[N] = E;
}

__global__ void scatter_kernel(const int* __restrict__ ei, int* __restrict__ cursor,
                               int* __restrict__ srcs, int E) {
    int base = (blockIdx.x * blockDim.x + threadIdx.x) * 8;
    if (base >= E) return;
    if (base + 8 <= E) {
        int s[8], p[8];
        const int4* ps = (const int4*)(ei + base);
        const int4* pd = (const int4*)(ei + E + base);
        int4 s0 = ps[0], s1 = ps[1];
        int4 d0 = pd[0], d1 = pd[1];
        s[0] = s0.x; s[1] = s0.y; s[2] = s0.z; s[3] = s0.w;
        s[4] = s1.x; s[5] = s1.y; s[6] = s1.z; s[7] = s1.w;
        p[0] = atomicAdd(cursor + d0.x, 1);
        p[1] = atomicAdd(cursor + d0.y, 1);
        p[2] = atomicAdd(cursor + d0.z, 1);
        p[3] = atomicAdd(cursor + d0.w, 1);
        p[4] = atomicAdd(cursor + d1.x, 1);
        p[5] = atomicAdd(cursor + d1.y, 1);
        p[6] = atomicAdd(cursor + d1.z, 1);
        p[7] = atomicAdd(cursor + d1.w, 1);
#pragma unroll
        for (int j = 0; j < 8; j++) srcs[p[j]] = s[j];
    } else {
        for (int e = base; e < E; e++) {
            int sv = ei[e];
            int pv = atomicAdd(cursor + ei[E + e], 1);
            srcs[pv] = sv;
        }
    }
}

// ---------------- fused softmax + aggregate + pool (warp per dst node) --------
#define CAP 64
__global__ __launch_bounds__(256, 6) void agg_fused(const int* __restrict__ off,
                                                    const int* __restrict__ srcs,
                                                    const float* __restrict__ esrc,
                                                    const float* __restrict__ edst,
                                                    const __half2* __restrict__ hh,
                                                    const int* __restrict__ batch,
                                                    float* __restrict__ pooled, int N) {
    __shared__ int   sh_src[8][CAP];
    __shared__ float sh_al[8][4][CAP + 1];
    int wi = threadIdx.x >> 5;
    int w = (blockIdx.x * blockDim.x + threadIdx.x) >> 5;
    int lane = threadIdx.x & 31;
    if (w >= N) return;
    int g = batch[w];
    int beg = off[w], end = off[w + 1];
    int deg = end - beg;
    if (deg == 0) return;

    float4 b = *(const float4*)(edst + w * 4);

    float4 dsum = make_float4(0.f, 0.f, 0.f, 0.f);
    for (int i = lane; i < deg; i += 32) {
        int s = srcs[beg + i];
        float4 a = *(const float4*)(esrc + s * 4);
        float ex0 = __expf(lrelu(a.x + b.x));
        float ex1 = __expf(lrelu(a.y + b.y));
        float ex2 = __expf(lrelu(a.z + b.z));
        float ex3 = __expf(lrelu(a.w + b.w));
        if (i < CAP) {
            sh_src[wi][i] = s;
            sh_al[wi][0][i] = ex0;
            sh_al[wi][1][i] = ex1;
            sh_al[wi][2][i] = ex2;
            sh_al[wi][3][i] = ex3;
        }
        dsum.x += ex0; dsum.y += ex1; dsum.z += ex2; dsum.w += ex3;
    }
#pragma unroll
    for (int d = 16; d; d >>= 1) {
        dsum.x += __shfl_xor_sync(0xFFFFFFFFu, dsum.x, d);
        dsum.y += __shfl_xor_sync(0xFFFFFFFFu, dsum.y, d);
        dsum.z += __shfl_xor_sync(0xFFFFFFFFu, dsum.z, d);
        dsum.w += __shfl_xor_sync(0xFFFFFFFFu, dsum.w, d);
    }
    __syncwarp();

    int h = lane >> 3;
    float bh  = (h == 0) ? b.x : (h == 1) ? b.y : (h == 2) ? b.z : b.w;
    float dh  = (h == 0) ? dsum.x : (h == 1) ? dsum.y : (h == 2) ? dsum.z : dsum.w;
    float inv = 1.0f / dh;

    const float* alp = sh_al[wi][h];
    const int*   sp  = sh_src[wi];
    const __half2* hbase = hh + lane * 2;

    float4 acc0 = make_float4(0.f, 0.f, 0.f, 0.f);
    float4 acc1 = make_float4(0.f, 0.f, 0.f, 0.f);
    int nfast = (deg < CAP) ? deg : CAP;
    int i = 0;
    for (; i + 1 < nfast; i += 2) {
        int s0 = sp[i], s1 = sp[i + 1];
        float al0 = alp[i] * inv, al1 = alp[i + 1] * inv;
        uint2 r0 = *(const uint2*)(hbase + (size_t)s0 * 64);
        uint2 r1 = *(const uint2*)(hbase + (size_t)s1 * 64);
        float2 a0 = __half22float2(*(__half2*)&r0.x);
        float2 b0v = __half22float2(*(__half2*)&r0.y);
        float2 a1 = __half22float2(*(__half2*)&r1.x);
        float2 b1v = __half22float2(*(__half2*)&r1.y);
        acc0.x += al0 * a0.x;  acc0.y += al0 * a0.y;
        acc0.z += al0 * b0v.x; acc0.w += al0 * b0v.y;
        acc1.x += al1 * a1.x;  acc1.y += al1 * a1.y;
        acc1.z += al1 * b1v.x; acc1.w += al1 * b1v.y;
    }
    for (; i < nfast; i++) {
        int s = sp[i];
        float alpha = alp[i] * inv;
        uint2 r = *(const uint2*)(hbase + (size_t)s * 64);
        float2 v0 = __half22float2(*(__half2*)&r.x);
        float2 v1 = __half22float2(*(__half2*)&r.y);
        acc0.x += alpha * v0.x; acc0.y += alpha * v0.y;
        acc0.z += alpha * v1.x; acc0.w += alpha * v1.y;
    }
    for (int j = CAP; j < deg; j++) {
        int s = srcs[beg + j];
        float alpha = __expf(lrelu(esrc[s * 4 + h] + bh)) * inv;
        uint2 r = *(const uint2*)(hbase + (size_t)s * 64);
        float2 v0 = __half22float2(*(__half2*)&r.x);
        float2 v1 = __half22float2(*(__half2*)&r.y);
        acc0.x += alpha * v0.x; acc0.y += alpha * v0.y;
        acc0.z += alpha * v1.x; acc0.w += alpha * v1.y;
    }
    red_add_v4(pooled + g * 128 + lane * 4,
               make_float4(acc0.x + acc1.x, acc0.y + acc1.y,
                           acc0.z + acc1.z, acc0.w + acc1.w));
}

// ---------------- classifier: warp per graph; counts via bsearch on batch -----
__global__ __launch_bounds__(1024) void classifier(const float* __restrict__ pooled,
                                                   const int* __restrict__ batch,
                                                   const float* __restrict__ Wc1,
                                                   const float* __restrict__ bc1,
                                                   const float* __restrict__ Wc2,
                                                   const float* __restrict__ bc2,
                                                   float* __restrict__ outp, int N) {
    __shared__ float sW1[128 * 64];
    __shared__ float srow[32][128];
    int t = threadIdx.x;
    int warp = t >> 5, lane = t & 31;
    int g = blockIdx.x * 32 + warp;
    for (int i = t; i < 8192; i += 1024) sW1[i] = Wc1[i];

    // count = #nodes with batch == g (batch sorted ascending)
    int cnt;
    if (lane == 0) {
        int lo = 0, hi = N;
        while (lo < hi) { int m = (lo + hi) >> 1; if (batch[m] < g) lo = m + 1; else hi = m; }
        int lb = lo;
        lo = 0; hi = N;
        while (lo < hi) { int m = (lo + hi) >> 1; if (batch[m] < g + 1) lo = m + 1; else hi = m; }
        cnt = lo - lb;
    }
    cnt = __shfl_sync(0xFFFFFFFFu, cnt, 0);
    float inv = 1.0f / fmaxf((float)cnt, 1.0f);

    float4 rv = *(const float4*)(pooled + g * 128 + lane * 4);
    srow[warp][lane * 4 + 0] = rv.x * inv;
    srow[warp][lane * 4 + 1] = rv.y * inv;
    srow[warp][lane * 4 + 2] = rv.z * inv;
    srow[warp][lane * 4 + 3] = rv.w * inv;
    __syncthreads();

    int j0 = lane * 2;
    float s0 = bc1[j0], s1 = bc1[j0 + 1];
#pragma unroll 8
    for (int k = 0; k < 128; k++) {
        float r = srow[warp][k];
        s0 += r * sW1[k * 64 + j0];
        s1 += r * sW1[k * 64 + j0 + 1];
    }
    s0 = fmaxf(s0, 0.f);
    s1 = fmaxf(s1, 0.f);
    float o0 = s0 * Wc2[j0 * 2]     + s1 * Wc2[(j0 + 1) * 2];
    float o1 = s0 * Wc2[j0 * 2 + 1] + s1 * Wc2[(j0 + 1) * 2 + 1];
#pragma unroll
    for (int d = 16; d; d >>= 1) {
        o0 += __shfl_xor_sync(0xFFFFFFFFu, o0, d);
        o1 += __shfl_xor_sync(0xFFFFFFFFu, o1, d);
    }
    if (lane == 0) {
        outp[g * 2 + 0] = o0 + bc2[0];
        outp[g * 2 + 1] = o1 + bc2[1];
    }
}

// ---------------- launch ------------------------------------------------------
extern "C" void kernel_launch(void* const* d_in, const int* in_sizes, int n_in,
                              void* d_out, int out_size) {
    const float* x      = (const float*)d_in[0];
    const int*   ei     = (const int*)d_in[1];
    const int*   batch  = (const int*)d_in[2];
    const float* W_proj = (const float*)d_in[3];
    const float* b_proj = (const float*)d_in[4];
    const float* W_gat  = (const float*)d_in[5];
    const float* a_src  = (const float*)d_in[6];
    const float* a_dst  = (const float*)d_in[7];
    const float* Wc1    = (const float*)d_in[8];
    const float* bc1    = (const float*)d_in[9];
    const float* Wc2    = (const float*)d_in[10];
    const float* bc2    = (const float*)d_in[11];

    int N = in_sizes[0] / 128;
    int E = in_sizes[1] / 2;

    __half2* p_hh;
    float *p_Wcomb, *p_bcomb, *p_esrc, *p_edst, *p_pooled;
    int *p_deg, *p_off, *p_cursor, *p_srcs, *p_flag, *p_agg;
    cudaGetSymbolAddress((void**)&p_hh, g_hh);
    cudaGetSymbolAddress((void**)&p_Wcomb, g_Wcomb);
    cudaGetSymbolAddress((void**)&p_bcomb, g_bcomb);
    cudaGetSymbolAddress((void**)&p_esrc, g_esrc);
    cudaGetSymbolAddress((void**)&p_edst, g_edst);
    cudaGetSymbolAddress((void**)&p_deg, g_deg);
    cudaGetSymbolAddress((void**)&p_off, g_off);
    cudaGetSymbolAddress((void**)&p_cursor, g_cursor);
    cudaGetSymbolAddress((void**)&p_srcs, g_srcsort);
    cudaGetSymbolAddress((void**)&p_flag, g_flag);
    cudaGetSymbolAddress((void**)&p_agg, g_agg);
    cudaGetSymbolAddress((void**)&p_pooled, g_pooled);

    const int GEMM_SMEM = (16384 + 64 * AT_LD) * 4;
    cudaFuncSetAttribute(gemm128h, cudaFuncAttributeMaxDynamicSharedMemorySize, GEMM_SMEM);

    cudaStream_t s2;
    cudaEvent_t ev_fork, ev_join;
    cudaStreamCreateWithFlags(&s2, cudaStreamNonBlocking);
    cudaEventCreateWithFlags(&ev_fork, cudaEventDisableTiming);
    cudaEventCreateWithFlags(&ev_join, cudaEventDisableTiming);

    int nb = (N + 1023) / 1024;

    // ---- stream 0: init, then fork
    init_kernel<<<(N + 255) / 256, 256>>>(p_deg, p_pooled, p_flag, N);
    cudaEventRecord(ev_fork, 0);

    // ---- side stream: CSR build
    cudaStreamWaitEvent(s2, ev_fork, 0);
    hist_kernel<<<(E / 16 + 255) / 256, 256, 0, s2>>>(ei, p_deg, E);
    scan_fused<<<nb, 256, 0, s2>>>(p_deg, p_off, p_cursor, p_flag, p_agg, N, E);
    scatter_kernel<<<(E / 8 + 255) / 256, 256, 0, s2>>>(ei, p_cursor, p_srcs, E);
    cudaEventRecord(ev_join, s2);

    // ---- stream 0: weights + hh (+fused attention coefs)
    wcomb_bias<<<65, 256>>>(W_proj, W_gat, b_proj, p_Wcomb, p_bcomb);
    gemm128h<<<(N + 127) / 128, 256, GEMM_SMEM>>>(x, p_Wcomb, p_bcomb, a_src, a_dst,
                                                  p_hh, p_esrc, p_edst, N);

    // ---- join, aggregate, classify
    cudaStreamWaitEvent(0, ev_join, 0);
    agg_fused<<<(N * 32 + 255) / 256, 256>>>(p_off, p_srcs, p_esrc, p_edst,
                                             p_hh, batch, p_pooled, N);
    classifier<<<2, 1024>>>(p_pooled, batch, Wc1, bc1, Wc2, bc2, (float*)d_out, N);
}